// round 12
// baseline (speedup 1.0000x reference)
#include <cuda_runtime.h>
#include <cuda_bf16.h>
#include <math.h>
#include <stdint.h>

#define BB 4
#define TT 2048
#define DM 1024
#define NH 16
#define DH 64
#define M_TOT (BB*TT)   // 8192

// Scratch (allocation-free rule: device globals), all bf16 split planes
__device__ __nv_bfloat16 g_qkvh[(size_t)BB*TT*3*DM];  // qkv hi [B,T,3D]
__device__ __nv_bfloat16 g_qkvl[(size_t)BB*TT*3*DM];  // qkv lo
__device__ __nv_bfloat16 g_ah[(size_t)M_TOT*DM];      // x-split, then att-split (hi)
__device__ __nv_bfloat16 g_al[(size_t)M_TOT*DM];      // (lo)
__device__ __nv_bfloat16 g_wh[(size_t)3*DM*DM];       // weight splits (hi)
__device__ __nv_bfloat16 g_wl[(size_t)3*DM*DM];       // (lo)

// ===========================================================================
// Portable (sm_100 base target) tensor-core primitives. tcgen05 is sm_100a-
// only and this harness compiles at sm_100 — mma.sync/ldmatrix/cp.async only.
// ===========================================================================
__device__ __forceinline__ uint32_t smem_u32(const void* p) {
    uint32_t a;
    asm("{ .reg .u64 t; cvta.to.shared.u64 t, %1; cvt.u32.u64 %0, t; }" : "=r"(a) : "l"(p));
    return a;
}
__device__ __forceinline__ void ldsm4(uint32_t* r, uint32_t addr) {
    asm volatile("ldmatrix.sync.aligned.m8n8.x4.shared.b16 {%0,%1,%2,%3}, [%4];"
        : "=r"(r[0]), "=r"(r[1]), "=r"(r[2]), "=r"(r[3]) : "r"(addr));
}
__device__ __forceinline__ void ldsm4t(uint32_t* r, uint32_t addr) {
    asm volatile("ldmatrix.sync.aligned.m8n8.x4.trans.shared.b16 {%0,%1,%2,%3}, [%4];"
        : "=r"(r[0]), "=r"(r[1]), "=r"(r[2]), "=r"(r[3]) : "r"(addr));
}
__device__ __forceinline__ void mma_bf16(float* d, const uint32_t* a, const uint32_t* b) {
    asm volatile("mma.sync.aligned.m16n8k16.row.col.f32.bf16.bf16.f32 "
        "{%0,%1,%2,%3}, {%4,%5,%6,%7}, {%8,%9}, {%0,%1,%2,%3};"
        : "+f"(d[0]), "+f"(d[1]), "+f"(d[2]), "+f"(d[3])
        : "r"(a[0]), "r"(a[1]), "r"(a[2]), "r"(a[3]), "r"(b[0]), "r"(b[1]));
}
#define CP_ASYNC16(s, g) \
    asm volatile("cp.async.cg.shared.global [%0], [%1], 16;" :: "r"(s), "l"(g))
#define CP_COMMIT() asm volatile("cp.async.commit_group;" ::: "memory")
template <int N> __device__ __forceinline__ void cp_wait() {
    asm volatile("cp.async.wait_group %0;" :: "n"(N) : "memory");
}
__device__ __forceinline__ float ex2(float x) {
    float y;
    asm("ex2.approx.ftz.f32 %0, %1;" : "=f"(y) : "f"(x));
    return y;
}
__device__ __forceinline__ void splitpack(float a, float b, uint32_t& hi, uint32_t& lo) {
    __nv_bfloat16 ha = __float2bfloat16(a), hb = __float2bfloat16(b);
    __nv_bfloat16 la = __float2bfloat16(a - __bfloat162float(ha));
    __nv_bfloat16 lb = __float2bfloat16(b - __bfloat162float(hb));
    hi = (uint32_t)__bfloat16_as_ushort(ha) | ((uint32_t)__bfloat16_as_ushort(hb) << 16);
    lo = (uint32_t)__bfloat16_as_ushort(la) | ((uint32_t)__bfloat16_as_ushort(lb) << 16);
}

// ===========================================================================
// fp32 -> bf16 (hi, lo) split pass:  v = hi + lo + O(2^-17 |v|)
// ===========================================================================
__global__ __launch_bounds__(256) void split_bf16(
    const float* __restrict__ src, __nv_bfloat16* __restrict__ hi,
    __nv_bfloat16* __restrict__ lo, int n)
{
    int i = (blockIdx.x * 256 + threadIdx.x) * 4;
    if (i >= n) return;
    float4 v = *(const float4*)(src + i);
    uint2 hp, lp;
    splitpack(v.x, v.y, hp.x, lp.x);
    splitpack(v.z, v.w, hp.y, lp.y);
    *(uint2*)(hi + i) = hp;
    *(uint2*)(lo + i) = lp;
}

// ===========================================================================
// HMMA bf16-split GEMM (NT): C = A * B^T, fp32 accumulate.
// CTA 128x128, 8 warps (2x4), warp tile 64x32, BK=32, 2-stage double buffer,
// two barriers per chunk, 2 CTAs/SM.  Rows padded 64B->80B.
// B fragments via ldsm4 over 16-row spans (b(nt)={r0,r2}, b(nt+1)={r1,r3})
// — halves the B LDSM instruction count vs ldsm2.
// ===========================================================================
#define BK 32
#define ABYTES (128*80)
#define STG    (4*ABYTES)
#define GSMEM  (2*STG)               // 81920 B

template <bool SPLIT>
__global__ __launch_bounds__(256, 2) void gemm_mma(
    const __nv_bfloat16* __restrict__ Ah, const __nv_bfloat16* __restrict__ Al,
    const __nv_bfloat16* __restrict__ Bh, const __nv_bfloat16* __restrict__ Bl,
    float* __restrict__ C, __nv_bfloat16* __restrict__ Ch, __nv_bfloat16* __restrict__ Cl,
    int N, int K, float qscale)
{
    extern __shared__ char smem[];
    const uint32_t sb = smem_u32(smem);
    const int tid = threadIdx.x, lane = tid & 31, wid = tid >> 5;
    const int wm = wid >> 2, wn = wid & 3;
    const int mBlk = blockIdx.y * 128, nBlk = blockIdx.x * 128;

    float acc[4][4][4];
#pragma unroll
    for (int mt = 0; mt < 4; mt++)
#pragma unroll
        for (int nt = 0; nt < 4; nt++)
#pragma unroll
            for (int j = 0; j < 4; j++) acc[mt][nt][j] = 0.f;

    const int NCH = K / BK;

    auto load_stage = [&](int s, int k0) {
        uint32_t so = sb + (s ? STG : 0);
#pragma unroll
        for (int i = tid; i < 512; i += 256) {
            int r = i >> 2, ch = i & 3;
            uint32_t d = so + (uint32_t)r * 80 + ch * 16;
            size_t goA = (size_t)(mBlk + r) * K + k0 + ch * 8;
            size_t goB = (size_t)(nBlk + r) * K + k0 + ch * 8;
            CP_ASYNC16(d,            Ah + goA);
            CP_ASYNC16(d + ABYTES,   Al + goA);
            CP_ASYNC16(d + 2*ABYTES, Bh + goB);
            CP_ASYNC16(d + 3*ABYTES, Bl + goB);
        }
        CP_COMMIT();
    };

    load_stage(0, 0);

    for (int c = 0; c < NCH; c++) {
        if (c + 1 < NCH) { load_stage((c + 1) & 1, (c + 1) * BK); cp_wait<1>(); }
        else             { cp_wait<0>(); }
        __syncthreads();

        uint32_t so = sb + ((c & 1) ? STG : 0);
        const uint32_t aRow = wm * 64 + (lane & 15);
        const uint32_t bRow = wn * 32 + (lane & 15);
#pragma unroll
        for (int ks = 0; ks < 2; ks++) {
            const uint32_t kk = ks * 16 + (lane >> 4) * 8;   // halves
            uint32_t ah[4][4], al[4][4];
#pragma unroll
            for (int mt = 0; mt < 4; mt++) {
                uint32_t addr = so + (aRow + mt * 16) * 80 + kk * 2;
                ldsm4(ah[mt], addr);
                ldsm4(al[mt], addr + ABYTES);
            }
#pragma unroll
            for (int ntp = 0; ntp < 2; ntp++) {
                uint32_t baddr = so + 2*ABYTES + (bRow + ntp * 16) * 80 + kk * 2;
                uint32_t bh4[4], bl4[4];
                ldsm4(bh4, baddr);
                ldsm4(bl4, baddr + ABYTES);
#pragma unroll
                for (int sub = 0; sub < 2; sub++) {
                    int nt = ntp * 2 + sub;
                    uint32_t bh[2] = {bh4[sub], bh4[sub + 2]};
                    uint32_t bl[2] = {bl4[sub], bl4[sub + 2]};
#pragma unroll
                    for (int mt = 0; mt < 4; mt++) {
                        mma_bf16(acc[mt][nt], ah[mt], bh);
                        mma_bf16(acc[mt][nt], ah[mt], bl);
                        mma_bf16(acc[mt][nt], al[mt], bh);
                    }
                }
            }
        }
        __syncthreads();
    }

    const float sc = (nBlk < DM) ? qscale : 1.0f;
    const int row0 = mBlk + wm * 64, col0 = nBlk + wn * 32;
#pragma unroll
    for (int mt = 0; mt < 4; mt++) {
        int r = row0 + mt * 16 + (lane >> 2);
#pragma unroll
        for (int nt = 0; nt < 4; nt++) {
            int cc = col0 + nt * 8 + (lane & 3) * 2;
            float v0 = acc[mt][nt][0] * sc, v1 = acc[mt][nt][1] * sc;
            float v2 = acc[mt][nt][2] * sc, v3 = acc[mt][nt][3] * sc;
            if (SPLIT) {
                uint32_t h0, l0, h1, l1;
                splitpack(v0, v1, h0, l0);
                splitpack(v2, v3, h1, l1);
                *(uint32_t*)(Ch + (size_t)r * N + cc)       = h0;
                *(uint32_t*)(Cl + (size_t)r * N + cc)       = l0;
                *(uint32_t*)(Ch + (size_t)(r + 8) * N + cc) = h1;
                *(uint32_t*)(Cl + (size_t)(r + 8) * N + cc) = l1;
            } else {
                *(float2*)(C + (size_t)r * N + cc)       = make_float2(v0, v1);
                *(float2*)(C + (size_t)(r + 8) * N + cc) = make_float2(v2, v3);
            }
        }
    }
}

// ===========================================================================
// Tensor-core flash attention (R10 version — reverted from the R11 software
// pipeline, which regressed: mma.sync is synchronous, there was no result
// stall to hide).  bf16-split, fp32 accum, key tile 32, 3-stage cp.async,
// one barrier per tile, 2 CTAs/SM.  Rows 128 B data + 16 B pad.
// smem: Qh Ql (128x144) | 3 stages x {Kh,Kl,Vh,Vl} (32x144 each) = 92160 B.
// ===========================================================================
#define FROW 144
#define QPL  (128*FROW)       // 18432 per Q plane
#define KVPL (32*FROW)        // 4608 per K/V plane
#define SQH 0
#define SQL QPL
#define SKV (2*QPL)           // 36864
#define KVSTG (4*KVPL)        // 18432 per stage
#define FSMEM (SKV + 3*KVSTG) // 92160

__global__ __launch_bounds__(256, 2) void flash_tc(
    const __nv_bfloat16* __restrict__ Ph, const __nv_bfloat16* __restrict__ Pl,
    __nv_bfloat16* __restrict__ Oh, __nv_bfloat16* __restrict__ Ol)
{
    extern __shared__ char smem[];
    const uint32_t sb = smem_u32(smem);
    const int tid = threadIdx.x, lane = tid & 31, wid = tid >> 5;
    const int qt = blockIdx.x, bh = blockIdx.y;
    const int b = bh >> 4, h = bh & 15;
    const size_t rowbase = (size_t)b * TT;
    const int q0 = qt * 128;
    const int hoff = h * DH;

    // ---- Q tile (hi/lo), 128 rows x 64 halves, cp.async (group 0, with kv0)
#pragma unroll
    for (int i = tid; i < 2048; i += 256) {
        int pl = i >> 10, r = (i >> 3) & 127, ch = i & 7;
        const __nv_bfloat16* src = (pl ? Pl : Ph) + (rowbase + q0 + r) * 3*DM + hoff + ch * 8;
        CP_ASYNC16(sb + (pl ? SQL : SQH) + r * FROW + ch * 16, src);
    }
    auto load_kv = [&](int s, int kt) {
        uint32_t so = sb + SKV + s * KVSTG;
#pragma unroll
        for (int i = tid; i < 1024; i += 256) {
            int p = i >> 8, r = (i >> 3) & 31, ch = i & 7;
            const __nv_bfloat16* basep = (p & 1) ? Pl : Ph;
            int sec = (p >> 1) ? 2*DM : DM;
            const __nv_bfloat16* src = basep + (rowbase + kt*32 + r) * 3*DM + sec + hoff + ch * 8;
            CP_ASYNC16(so + p * KVPL + r * FROW + ch * 16, src);
        }
    };
    load_kv(0, 0);
    CP_COMMIT();
    load_kv(1, 1);
    CP_COMMIT();

    const int wq = wid * 16;
    const int NK = TT / 32;
    float o[8][4];
#pragma unroll
    for (int j = 0; j < 8; j++)
#pragma unroll
        for (int i = 0; i < 4; i++) o[j][i] = 0.f;
    float m0 = -1e30f, m1 = -1e30f, l0 = 0.f, l1 = 0.f;

    for (int kt = 0; kt < NK; kt++) {
        if (kt + 1 < NK) cp_wait<1>(); else cp_wait<0>();
        __syncthreads();
        if (kt + 2 < NK) { load_kv((kt + 2) % 3, kt + 2); CP_COMMIT(); }
        const uint32_t kvb = sb + SKV + (kt % 3) * KVSTG;

        // ---- S = Q K^T  (split: QhKh + QhKl + QlKh), 16q x 32k per warp
        float s[4][4];
#pragma unroll
        for (int j = 0; j < 4; j++)
#pragma unroll
            for (int i = 0; i < 4; i++) s[j][i] = 0.f;
#pragma unroll
        for (int ks = 0; ks < 4; ks++) {
            uint32_t qaddr = sb + SQH + (wq + (lane & 15)) * FROW + (ks*16 + (lane >> 4)*8) * 2;
            uint32_t qh[4], ql[4];
            ldsm4(qh, qaddr);
            ldsm4(ql, qaddr + SQL);
#pragma unroll
            for (int np = 0; np < 2; np++) {
                uint32_t kaddr = kvb + (np*16 + (lane & 15)) * FROW + (ks*16 + (lane >> 4)*8) * 2;
                uint32_t kh[4], kl[4];
                ldsm4(kh, kaddr);
                ldsm4(kl, kaddr + KVPL);
                uint32_t b0h[2] = {kh[0], kh[2]}, b1h[2] = {kh[1], kh[3]};
                uint32_t b0l[2] = {kl[0], kl[2]}, b1l[2] = {kl[1], kl[3]};
                mma_bf16(s[2*np],   qh, b0h);
                mma_bf16(s[2*np],   qh, b0l);
                mma_bf16(s[2*np],   ql, b0h);
                mma_bf16(s[2*np+1], qh, b1h);
                mma_bf16(s[2*np+1], qh, b1l);
                mma_bf16(s[2*np+1], ql, b1h);
            }
        }

        // ---- online softmax (log2 domain; scale already folded into Q)
        float t0 = -1e30f, t1 = -1e30f;
#pragma unroll
        for (int j = 0; j < 4; j++) {
            t0 = fmaxf(t0, fmaxf(s[j][0], s[j][1]));
            t1 = fmaxf(t1, fmaxf(s[j][2], s[j][3]));
        }
        t0 = fmaxf(t0, __shfl_xor_sync(0xffffffffu, t0, 1));
        t0 = fmaxf(t0, __shfl_xor_sync(0xffffffffu, t0, 2));
        t1 = fmaxf(t1, __shfl_xor_sync(0xffffffffu, t1, 1));
        t1 = fmaxf(t1, __shfl_xor_sync(0xffffffffu, t1, 2));
        float m0n = fmaxf(m0, t0), m1n = fmaxf(m1, t1);
        float r0 = ex2(m0 - m0n), r1 = ex2(m1 - m1n);
        m0 = m0n; m1 = m1n;

        float ls0 = 0.f, ls1 = 0.f;
        uint32_t aph[2][4], apl[2][4];
#pragma unroll
        for (int j = 0; j < 4; j++) {
            float p0 = ex2(s[j][0] - m0), p1 = ex2(s[j][1] - m0);
            float p2 = ex2(s[j][2] - m1), p3 = ex2(s[j][3] - m1);
            ls0 += p0 + p1; ls1 += p2 + p3;
            int jj = j >> 1, rb = (j & 1) * 2;
            splitpack(p0, p1, aph[jj][rb],     apl[jj][rb]);
            splitpack(p2, p3, aph[jj][rb + 1], apl[jj][rb + 1]);
        }
        ls0 += __shfl_xor_sync(0xffffffffu, ls0, 1);
        ls0 += __shfl_xor_sync(0xffffffffu, ls0, 2);
        ls1 += __shfl_xor_sync(0xffffffffu, ls1, 1);
        ls1 += __shfl_xor_sync(0xffffffffu, ls1, 2);
        l0 = l0 * r0 + ls0;
        l1 = l1 * r1 + ls1;
#pragma unroll
        for (int j = 0; j < 8; j++) {
            o[j][0] *= r0; o[j][1] *= r0; o[j][2] *= r1; o[j][3] *= r1;
        }

        // ---- O += P V  (split: PhVh + PhVl + PlVh), V via ldmatrix.trans
#pragma unroll
        for (int jj = 0; jj < 2; jj++) {
#pragma unroll
            for (int np = 0; np < 4; np++) {
                uint32_t vaddr = kvb + 2*KVPL + (jj*16 + (lane & 15)) * FROW + (np*16 + (lane >> 4)*8) * 2;
                uint32_t vh[4], vl[4];
                ldsm4t(vh, vaddr);
                ldsm4t(vl, vaddr + KVPL);
                uint32_t bh0[2] = {vh[0], vh[1]}, bh1[2] = {vh[2], vh[3]};
                uint32_t bl0[2] = {vl[0], vl[1]}, bl1[2] = {vl[2], vl[3]};
                mma_bf16(o[2*np],   aph[jj], bh0);
                mma_bf16(o[2*np],   aph[jj], bl0);
                mma_bf16(o[2*np],   apl[jj], bh0);
                mma_bf16(o[2*np+1], aph[jj], bh1);
                mma_bf16(o[2*np+1], aph[jj], bl1);
                mma_bf16(o[2*np+1], apl[jj], bh1);
            }
        }
    }

    // ---- epilogue: normalize, split, write att hi/lo planes [B,T,D]
    float inv0 = 1.f / l0, inv1 = 1.f / l1;
    const size_t rA = rowbase + q0 + wq + (lane >> 2);
    const size_t rB = rA + 8;
#pragma unroll
    for (int j = 0; j < 8; j++) {
        int col = hoff + j * 8 + (lane & 3) * 2;
        uint32_t h0, lo0, h1, lo1;
        splitpack(o[j][0] * inv0, o[j][1] * inv0, h0, lo0);
        splitpack(o[j][2] * inv1, o[j][3] * inv1, h1, lo1);
        *(uint32_t*)(Oh + rA * DM + col) = h0;
        *(uint32_t*)(Ol + rA * DM + col) = lo0;
        *(uint32_t*)(Oh + rB * DM + col) = h1;
        *(uint32_t*)(Ol + rB * DM + col) = lo1;
    }
}

// ---------------------------------------------------------------------------
extern "C" void kernel_launch(void* const* d_in, const int* in_sizes, int n_in,
                              void* d_out, int out_size)
{
    const float* x      = (const float*)d_in[0];  // [4,2048,1024]
    const float* w_qkv  = (const float*)d_in[1];  // [3072,1024]
    const float* w_proj = (const float*)d_in[2];  // [1024,1024]
    float* out = (float*)d_out;                   // [4,2048,1024]

    void *qh_p, *ql_p, *ah_p, *al_p, *wh_p, *wl_p;
    cudaGetSymbolAddress(&qh_p, g_qkvh);
    cudaGetSymbolAddress(&ql_p, g_qkvl);
    cudaGetSymbolAddress(&ah_p, g_ah);
    cudaGetSymbolAddress(&al_p, g_al);
    cudaGetSymbolAddress(&wh_p, g_wh);
    cudaGetSymbolAddress(&wl_p, g_wl);
    __nv_bfloat16 *qkvh = (__nv_bfloat16*)qh_p, *qkvl = (__nv_bfloat16*)ql_p;
    __nv_bfloat16 *ah = (__nv_bfloat16*)ah_p, *al = (__nv_bfloat16*)al_p;
    __nv_bfloat16 *wh = (__nv_bfloat16*)wh_p, *wl = (__nv_bfloat16*)wl_p;

    cudaFuncSetAttribute(gemm_mma<true>,  cudaFuncAttributeMaxDynamicSharedMemorySize, GSMEM);
    cudaFuncSetAttribute(gemm_mma<false>, cudaFuncAttributeMaxDynamicSharedMemorySize, GSMEM);
    cudaFuncSetAttribute(flash_tc, cudaFuncAttributeMaxDynamicSharedMemorySize, FSMEM);

    const int nX = M_TOT * DM, nWq = 3 * DM * DM, nWp = DM * DM;
    const float CSC = 0.125f * 1.4426950408889634f;   // softmax scale * log2(e)

    // 1) split x, w_qkv; qkv = x @ w_qkv^T -> bf16 hi/lo planes directly
    //    (Q section pre-scaled by CSC in the epilogue)
    split_bf16<<<nX / 1024, 256>>>(x, ah, al, nX);
    split_bf16<<<nWq / 1024, 256>>>(w_qkv, wh, wl, nWq);
    gemm_mma<true><<<dim3(3*DM/128, M_TOT/128), 256, GSMEM>>>(
        ah, al, wh, wl, nullptr, qkvh, qkvl, 3*DM, DM, CSC);

    // 2) tensor-core flash attention -> att hi/lo planes (into g_ah/g_al)
    flash_tc<<<dim3(TT/128, BB*NH), 256, FSMEM>>>(qkvh, qkvl, ah, al);

    // 3) split w_proj; out = att @ w_proj^T (fp32 out)
    split_bf16<<<nWp / 1024, 256>>>(w_proj, wh, wl, nWp);
    gemm_mma<false><<<dim3(DM/128, M_TOT/128), 256, GSMEM>>>(
        ah, al, wh, wl, out, nullptr, nullptr, DM, DM, 1.0f);
}

// round 13
// speedup vs baseline: 1.2159x; 1.2159x over previous
#include <cuda_runtime.h>
#include <cuda_bf16.h>
#include <cuda_fp16.h>
#include <math.h>
#include <stdint.h>

#define BB 4
#define TT 2048
#define DM 1024
#define NH 16
#define DH 64
#define M_TOT (BB*TT)   // 8192

// Scratch (allocation-free rule: device globals)
__device__ __nv_bfloat16 g_qkvh[(size_t)BB*TT*3*DM];  // qkv hi [B,T,3D] bf16
__device__ __nv_bfloat16 g_qkvl[(size_t)BB*TT*3*DM];  // qkv lo bf16
__device__ __nv_bfloat16 g_ah[(size_t)M_TOT*DM];      // att-split hi (bf16, flash out)
__device__ __nv_bfloat16 g_al[(size_t)M_TOT*DM];      // att-split lo
__device__ __nv_bfloat16 g_wh[(size_t)DM*DM];         // w_proj split hi (bf16)
__device__ __nv_bfloat16 g_wl[(size_t)DM*DM];         // w_proj split lo
__device__ __half        g_xh[(size_t)M_TOT*DM];      // x as single fp16
__device__ __half        g_wh16[(size_t)3*DM*DM];     // w_qkv fp16 split hi
__device__ __half        g_wl16[(size_t)3*DM*DM];     // w_qkv fp16 split lo

// ===========================================================================
// Portable (sm_100 base target) tensor-core primitives. tcgen05 is sm_100a-
// only and this harness compiles at sm_100 — mma.sync/ldmatrix/cp.async only.
// ===========================================================================
__device__ __forceinline__ uint32_t smem_u32(const void* p) {
    uint32_t a;
    asm("{ .reg .u64 t; cvta.to.shared.u64 t, %1; cvt.u32.u64 %0, t; }" : "=r"(a) : "l"(p));
    return a;
}
__device__ __forceinline__ void ldsm4(uint32_t* r, uint32_t addr) {
    asm volatile("ldmatrix.sync.aligned.m8n8.x4.shared.b16 {%0,%1,%2,%3}, [%4];"
        : "=r"(r[0]), "=r"(r[1]), "=r"(r[2]), "=r"(r[3]) : "r"(addr));
}
__device__ __forceinline__ void ldsm4t(uint32_t* r, uint32_t addr) {
    asm volatile("ldmatrix.sync.aligned.m8n8.x4.trans.shared.b16 {%0,%1,%2,%3}, [%4];"
        : "=r"(r[0]), "=r"(r[1]), "=r"(r[2]), "=r"(r[3]) : "r"(addr));
}
__device__ __forceinline__ void ldsm2(uint32_t* r, uint32_t addr) {
    asm volatile("ldmatrix.sync.aligned.m8n8.x2.shared.b16 {%0,%1}, [%2];"
        : "=r"(r[0]), "=r"(r[1]) : "r"(addr));
}
__device__ __forceinline__ void mma_bf16(float* d, const uint32_t* a, const uint32_t* b) {
    asm volatile("mma.sync.aligned.m16n8k16.row.col.f32.bf16.bf16.f32 "
        "{%0,%1,%2,%3}, {%4,%5,%6,%7}, {%8,%9}, {%0,%1,%2,%3};"
        : "+f"(d[0]), "+f"(d[1]), "+f"(d[2]), "+f"(d[3])
        : "r"(a[0]), "r"(a[1]), "r"(a[2]), "r"(a[3]), "r"(b[0]), "r"(b[1]));
}
__device__ __forceinline__ void mma_f16(float* d, const uint32_t* a, const uint32_t* b) {
    asm volatile("mma.sync.aligned.m16n8k16.row.col.f32.f16.f16.f32 "
        "{%0,%1,%2,%3}, {%4,%5,%6,%7}, {%8,%9}, {%0,%1,%2,%3};"
        : "+f"(d[0]), "+f"(d[1]), "+f"(d[2]), "+f"(d[3])
        : "r"(a[0]), "r"(a[1]), "r"(a[2]), "r"(a[3]), "r"(b[0]), "r"(b[1]));
}
#define CP_ASYNC16(s, g) \
    asm volatile("cp.async.cg.shared.global [%0], [%1], 16;" :: "r"(s), "l"(g))
#define CP_COMMIT() asm volatile("cp.async.commit_group;" ::: "memory")
template <int N> __device__ __forceinline__ void cp_wait() {
    asm volatile("cp.async.wait_group %0;" :: "n"(N) : "memory");
}
__device__ __forceinline__ float ex2(float x) {
    float y;
    asm("ex2.approx.ftz.f32 %0, %1;" : "=f"(y) : "f"(x));
    return y;
}
__device__ __forceinline__ void splitpack(float a, float b, uint32_t& hi, uint32_t& lo) {
    __nv_bfloat16 ha = __float2bfloat16(a), hb = __float2bfloat16(b);
    __nv_bfloat16 la = __float2bfloat16(a - __bfloat162float(ha));
    __nv_bfloat16 lb = __float2bfloat16(b - __bfloat162float(hb));
    hi = (uint32_t)__bfloat16_as_ushort(ha) | ((uint32_t)__bfloat16_as_ushort(hb) << 16);
    lo = (uint32_t)__bfloat16_as_ushort(la) | ((uint32_t)__bfloat16_as_ushort(lb) << 16);
}
__device__ __forceinline__ void splitpack_h(float a, float b, uint32_t& hi, uint32_t& lo) {
    __half ha = __float2half_rn(a), hb = __float2half_rn(b);
    __half la = __float2half_rn(a - __half2float(ha));
    __half lb = __float2half_rn(b - __half2float(hb));
    hi = (uint32_t)__half_as_ushort(ha) | ((uint32_t)__half_as_ushort(hb) << 16);
    lo = (uint32_t)__half_as_ushort(la) | ((uint32_t)__half_as_ushort(lb) << 16);
}

// ===========================================================================
// fp32 -> bf16 (hi, lo) split  /  fp32 -> fp16 split  /  fp32 -> fp16 single
// ===========================================================================
__global__ __launch_bounds__(256) void split_bf16(
    const float* __restrict__ src, __nv_bfloat16* __restrict__ hi,
    __nv_bfloat16* __restrict__ lo, int n)
{
    int i = (blockIdx.x * 256 + threadIdx.x) * 4;
    if (i >= n) return;
    float4 v = *(const float4*)(src + i);
    uint2 hp, lp;
    splitpack(v.x, v.y, hp.x, lp.x);
    splitpack(v.z, v.w, hp.y, lp.y);
    *(uint2*)(hi + i) = hp;
    *(uint2*)(lo + i) = lp;
}
__global__ __launch_bounds__(256) void split_f16(
    const float* __restrict__ src, __half* __restrict__ hi,
    __half* __restrict__ lo, int n)
{
    int i = (blockIdx.x * 256 + threadIdx.x) * 4;
    if (i >= n) return;
    float4 v = *(const float4*)(src + i);
    uint2 hp, lp;
    splitpack_h(v.x, v.y, hp.x, lp.x);
    splitpack_h(v.z, v.w, hp.y, lp.y);
    *(uint2*)(hi + i) = hp;
    *(uint2*)(lo + i) = lp;
}
__global__ __launch_bounds__(256) void cvt_f16(
    const float* __restrict__ src, __half* __restrict__ dst, int n)
{
    int i = (blockIdx.x * 256 + threadIdx.x) * 4;
    if (i >= n) return;
    float4 v = *(const float4*)(src + i);
    __half2 p0 = __float22half2_rn(make_float2(v.x, v.y));
    __half2 p1 = __float22half2_rn(make_float2(v.z, v.w));
    uint2 p; p.x = *(uint32_t*)&p0; p.y = *(uint32_t*)&p1;
    *(uint2*)(dst + i) = p;
}

// ===========================================================================
// fp16 single-A GEMM (NT) for qkv: C = A * B^T, A single fp16 plane,
// B = fp16 2-term split (error 2^-22).  Dropped third term costs ~2.8e-4 rel.
// CTA 128x128, 8 warps (2x4), BK=32, 2-stage, two barriers/chunk, 2 CTAs/SM.
// Rows padded 64B->80B.  64 MMAs/chunk (vs 96 in the 3-term bf16 path).
// Epilogue: qscale on Q section, writes bf16 hi/lo planes for flash.
// ===========================================================================
#define BK 32
#define PBYTES (128*80)              // one plane per stage: 10240 B
#define FSTG   (3*PBYTES)            // A, Bh, Bl
#define F16SMEM (2*FSTG)             // 61440 B

__global__ __launch_bounds__(256, 2) void gemm_f16a1(
    const __half* __restrict__ A1,
    const __half* __restrict__ Bh, const __half* __restrict__ Bl,
    __nv_bfloat16* __restrict__ Ch, __nv_bfloat16* __restrict__ Cl,
    int N, int K, float qscale)
{
    extern __shared__ char smem[];
    const uint32_t sb = smem_u32(smem);
    const int tid = threadIdx.x, lane = tid & 31, wid = tid >> 5;
    const int wm = wid >> 2, wn = wid & 3;
    const int mBlk = blockIdx.y * 128, nBlk = blockIdx.x * 128;

    float acc[4][4][4];
#pragma unroll
    for (int mt = 0; mt < 4; mt++)
#pragma unroll
        for (int nt = 0; nt < 4; nt++)
#pragma unroll
            for (int j = 0; j < 4; j++) acc[mt][nt][j] = 0.f;

    const int NCH = K / BK;

    auto load_stage = [&](int s, int k0) {
        uint32_t so = sb + (s ? FSTG : 0);
#pragma unroll
        for (int i = tid; i < 512; i += 256) {
            int r = i >> 2, ch = i & 3;
            uint32_t d = so + (uint32_t)r * 80 + ch * 16;
            size_t goA = (size_t)(mBlk + r) * K + k0 + ch * 8;
            size_t goB = (size_t)(nBlk + r) * K + k0 + ch * 8;
            CP_ASYNC16(d,            A1 + goA);
            CP_ASYNC16(d + PBYTES,   Bh + goB);
            CP_ASYNC16(d + 2*PBYTES, Bl + goB);
        }
        CP_COMMIT();
    };

    load_stage(0, 0);

    for (int c = 0; c < NCH; c++) {
        if (c + 1 < NCH) { load_stage((c + 1) & 1, (c + 1) * BK); cp_wait<1>(); }
        else             { cp_wait<0>(); }
        __syncthreads();

        uint32_t so = sb + ((c & 1) ? FSTG : 0);
        const uint32_t aRow = wm * 64 + (lane & 15);
        const uint32_t bRow = wn * 32 + (lane & 7);
#pragma unroll
        for (int ks = 0; ks < 2; ks++) {
            const uint32_t ak = ks * 16 + (lane >> 4) * 8;
            const uint32_t bk = ks * 16 + ((lane >> 3) & 1) * 8;
            uint32_t ah[4][4];
#pragma unroll
            for (int mt = 0; mt < 4; mt++)
                ldsm4(ah[mt], so + (aRow + mt * 16) * 80 + ak * 2);
#pragma unroll
            for (int nt = 0; nt < 4; nt++) {
                uint32_t baddr = so + PBYTES + (bRow + nt * 8) * 80 + bk * 2;
                uint32_t bh[2], bl[2];
                ldsm2(bh, baddr);
                ldsm2(bl, baddr + PBYTES);
#pragma unroll
                for (int mt = 0; mt < 4; mt++) {
                    mma_f16(acc[mt][nt], ah[mt], bh);
                    mma_f16(acc[mt][nt], ah[mt], bl);
                }
            }
        }
        __syncthreads();
    }

    const float sc = (nBlk < DM) ? qscale : 1.0f;
    const int row0 = mBlk + wm * 64, col0 = nBlk + wn * 32;
#pragma unroll
    for (int mt = 0; mt < 4; mt++) {
        int r = row0 + mt * 16 + (lane >> 2);
#pragma unroll
        for (int nt = 0; nt < 4; nt++) {
            int cc = col0 + nt * 8 + (lane & 3) * 2;
            uint32_t h0, l0, h1, l1;
            splitpack(acc[mt][nt][0] * sc, acc[mt][nt][1] * sc, h0, l0);
            splitpack(acc[mt][nt][2] * sc, acc[mt][nt][3] * sc, h1, l1);
            *(uint32_t*)(Ch + (size_t)r * N + cc)       = h0;
            *(uint32_t*)(Cl + (size_t)r * N + cc)       = l0;
            *(uint32_t*)(Ch + (size_t)(r + 8) * N + cc) = h1;
            *(uint32_t*)(Cl + (size_t)(r + 8) * N + cc) = l1;
        }
    }
}

// ===========================================================================
// HMMA bf16-split GEMM (NT) — exact R10 version (proj only).
// CTA 128x128, 8 warps, BK=32, 2-stage, two barriers/chunk, 2 CTAs/SM.
// ===========================================================================
#define ABYTES (128*80)
#define STG    (4*ABYTES)
#define GSMEM  (2*STG)               // 81920 B

__global__ __launch_bounds__(256, 2) void gemm_bf16(
    const __nv_bfloat16* __restrict__ Ah, const __nv_bfloat16* __restrict__ Al,
    const __nv_bfloat16* __restrict__ Bh, const __nv_bfloat16* __restrict__ Bl,
    float* __restrict__ C, int N, int K)
{
    extern __shared__ char smem[];
    const uint32_t sb = smem_u32(smem);
    const int tid = threadIdx.x, lane = tid & 31, wid = tid >> 5;
    const int wm = wid >> 2, wn = wid & 3;
    const int mBlk = blockIdx.y * 128, nBlk = blockIdx.x * 128;

    float acc[4][4][4];
#pragma unroll
    for (int mt = 0; mt < 4; mt++)
#pragma unroll
        for (int nt = 0; nt < 4; nt++)
#pragma unroll
            for (int j = 0; j < 4; j++) acc[mt][nt][j] = 0.f;

    const int NCH = K / BK;

    auto load_stage = [&](int s, int k0) {
        uint32_t so = sb + (s ? STG : 0);
#pragma unroll
        for (int i = tid; i < 512; i += 256) {
            int r = i >> 2, ch = i & 3;
            uint32_t d = so + (uint32_t)r * 80 + ch * 16;
            size_t goA = (size_t)(mBlk + r) * K + k0 + ch * 8;
            size_t goB = (size_t)(nBlk + r) * K + k0 + ch * 8;
            CP_ASYNC16(d,            Ah + goA);
            CP_ASYNC16(d + ABYTES,   Al + goA);
            CP_ASYNC16(d + 2*ABYTES, Bh + goB);
            CP_ASYNC16(d + 3*ABYTES, Bl + goB);
        }
        CP_COMMIT();
    };

    load_stage(0, 0);

    for (int c = 0; c < NCH; c++) {
        if (c + 1 < NCH) { load_stage((c + 1) & 1, (c + 1) * BK); cp_wait<1>(); }
        else             { cp_wait<0>(); }
        __syncthreads();

        uint32_t so = sb + ((c & 1) ? STG : 0);
        const uint32_t aRow = wm * 64 + (lane & 15);
        const uint32_t bRow = wn * 32 + (lane & 7);
#pragma unroll
        for (int ks = 0; ks < 2; ks++) {
            const uint32_t ak = ks * 16 + (lane >> 4) * 8;
            const uint32_t bk = ks * 16 + ((lane >> 3) & 1) * 8;
            uint32_t ah[4][4], al[4][4];
#pragma unroll
            for (int mt = 0; mt < 4; mt++) {
                uint32_t addr = so + (aRow + mt * 16) * 80 + ak * 2;
                ldsm4(ah[mt], addr);
                ldsm4(al[mt], addr + ABYTES);
            }
#pragma unroll
            for (int nt = 0; nt < 4; nt++) {
                uint32_t baddr = so + 2*ABYTES + (bRow + nt * 8) * 80 + bk * 2;
                uint32_t bh[2], bl[2];
                ldsm2(bh, baddr);
                ldsm2(bl, baddr + ABYTES);
#pragma unroll
                for (int mt = 0; mt < 4; mt++) {
                    mma_bf16(acc[mt][nt], ah[mt], bh);
                    mma_bf16(acc[mt][nt], ah[mt], bl);
                    mma_bf16(acc[mt][nt], al[mt], bh);
                }
            }
        }
        __syncthreads();
    }

    const int row0 = mBlk + wm * 64, col0 = nBlk + wn * 32;
#pragma unroll
    for (int mt = 0; mt < 4; mt++) {
        int r = row0 + mt * 16 + (lane >> 2);
#pragma unroll
        for (int nt = 0; nt < 4; nt++) {
            int cc = col0 + nt * 8 + (lane & 3) * 2;
            *(float2*)(C + (size_t)r * N + cc)       = make_float2(acc[mt][nt][0], acc[mt][nt][1]);
            *(float2*)(C + (size_t)(r + 8) * N + cc) = make_float2(acc[mt][nt][2], acc[mt][nt][3]);
        }
    }
}

// ===========================================================================
// Tensor-core flash attention — exact R10 version (632 µs known).
// bf16-split, fp32 accum, key tile 32, 3-stage cp.async, one barrier/tile,
// 2 CTAs/SM.  Rows 128 B data + 16 B pad.
// ===========================================================================
#define FROW 144
#define QPL  (128*FROW)
#define KVPL (32*FROW)
#define SQH 0
#define SQL QPL
#define SKV (2*QPL)
#define KVSTG (4*KVPL)
#define FSMEM (SKV + 3*KVSTG) // 92160

__global__ __launch_bounds__(256, 2) void flash_tc(
    const __nv_bfloat16* __restrict__ Ph, const __nv_bfloat16* __restrict__ Pl,
    __nv_bfloat16* __restrict__ Oh, __nv_bfloat16* __restrict__ Ol)
{
    extern __shared__ char smem[];
    const uint32_t sb = smem_u32(smem);
    const int tid = threadIdx.x, lane = tid & 31, wid = tid >> 5;
    const int qt = blockIdx.x, bh = blockIdx.y;
    const int b = bh >> 4, h = bh & 15;
    const size_t rowbase = (size_t)b * TT;
    const int q0 = qt * 128;
    const int hoff = h * DH;

#pragma unroll
    for (int i = tid; i < 2048; i += 256) {
        int pl = i >> 10, r = (i >> 3) & 127, ch = i & 7;
        const __nv_bfloat16* src = (pl ? Pl : Ph) + (rowbase + q0 + r) * 3*DM + hoff + ch * 8;
        CP_ASYNC16(sb + (pl ? SQL : SQH) + r * FROW + ch * 16, src);
    }
    auto load_kv = [&](int s, int kt) {
        uint32_t so = sb + SKV + s * KVSTG;
#pragma unroll
        for (int i = tid; i < 1024; i += 256) {
            int p = i >> 8, r = (i >> 3) & 31, ch = i & 7;
            const __nv_bfloat16* basep = (p & 1) ? Pl : Ph;
            int sec = (p >> 1) ? 2*DM : DM;
            const __nv_bfloat16* src = basep + (rowbase + kt*32 + r) * 3*DM + sec + hoff + ch * 8;
            CP_ASYNC16(so + p * KVPL + r * FROW + ch * 16, src);
        }
    };
    load_kv(0, 0);
    CP_COMMIT();
    load_kv(1, 1);
    CP_COMMIT();

    const int wq = wid * 16;
    const int NK = TT / 32;
    float o[8][4];
#pragma unroll
    for (int j = 0; j < 8; j++)
#pragma unroll
        for (int i = 0; i < 4; i++) o[j][i] = 0.f;
    float m0 = -1e30f, m1 = -1e30f, l0 = 0.f, l1 = 0.f;

    for (int kt = 0; kt < NK; kt++) {
        if (kt + 1 < NK) cp_wait<1>(); else cp_wait<0>();
        __syncthreads();
        if (kt + 2 < NK) { load_kv((kt + 2) % 3, kt + 2); CP_COMMIT(); }
        const uint32_t kvb = sb + SKV + (kt % 3) * KVSTG;

        float s[4][4];
#pragma unroll
        for (int j = 0; j < 4; j++)
#pragma unroll
            for (int i = 0; i < 4; i++) s[j][i] = 0.f;
#pragma unroll
        for (int ks = 0; ks < 4; ks++) {
            uint32_t qaddr = sb + SQH + (wq + (lane & 15)) * FROW + (ks*16 + (lane >> 4)*8) * 2;
            uint32_t qh[4], ql[4];
            ldsm4(qh, qaddr);
            ldsm4(ql, qaddr + SQL);
#pragma unroll
            for (int np = 0; np < 2; np++) {
                uint32_t kaddr = kvb + (np*16 + (lane & 15)) * FROW + (ks*16 + (lane >> 4)*8) * 2;
                uint32_t kh[4], kl[4];
                ldsm4(kh, kaddr);
                ldsm4(kl, kaddr + KVPL);
                uint32_t b0h[2] = {kh[0], kh[2]}, b1h[2] = {kh[1], kh[3]};
                uint32_t b0l[2] = {kl[0], kl[2]}, b1l[2] = {kl[1], kl[3]};
                mma_bf16(s[2*np],   qh, b0h);
                mma_bf16(s[2*np],   qh, b0l);
                mma_bf16(s[2*np],   ql, b0h);
                mma_bf16(s[2*np+1], qh, b1h);
                mma_bf16(s[2*np+1], qh, b1l);
                mma_bf16(s[2*np+1], ql, b1h);
            }
        }

        float t0 = -1e30f, t1 = -1e30f;
#pragma unroll
        for (int j = 0; j < 4; j++) {
            t0 = fmaxf(t0, fmaxf(s[j][0], s[j][1]));
            t1 = fmaxf(t1, fmaxf(s[j][2], s[j][3]));
        }
        t0 = fmaxf(t0, __shfl_xor_sync(0xffffffffu, t0, 1));
        t0 = fmaxf(t0, __shfl_xor_sync(0xffffffffu, t0, 2));
        t1 = fmaxf(t1, __shfl_xor_sync(0xffffffffu, t1, 1));
        t1 = fmaxf(t1, __shfl_xor_sync(0xffffffffu, t1, 2));
        float m0n = fmaxf(m0, t0), m1n = fmaxf(m1, t1);
        float r0 = ex2(m0 - m0n), r1 = ex2(m1 - m1n);
        m0 = m0n; m1 = m1n;

        float ls0 = 0.f, ls1 = 0.f;
        uint32_t aph[2][4], apl[2][4];
#pragma unroll
        for (int j = 0; j < 4; j++) {
            float p0 = ex2(s[j][0] - m0), p1 = ex2(s[j][1] - m0);
            float p2 = ex2(s[j][2] - m1), p3 = ex2(s[j][3] - m1);
            ls0 += p0 + p1; ls1 += p2 + p3;
            int jj = j >> 1, rb = (j & 1) * 2;
            splitpack(p0, p1, aph[jj][rb],     apl[jj][rb]);
            splitpack(p2, p3, aph[jj][rb + 1], apl[jj][rb + 1]);
        }
        ls0 += __shfl_xor_sync(0xffffffffu, ls0, 1);
        ls0 += __shfl_xor_sync(0xffffffffu, ls0, 2);
        ls1 += __shfl_xor_sync(0xffffffffu, ls1, 1);
        ls1 += __shfl_xor_sync(0xffffffffu, ls1, 2);
        l0 = l0 * r0 + ls0;
        l1 = l1 * r1 + ls1;
#pragma unroll
        for (int j = 0; j < 8; j++) {
            o[j][0] *= r0; o[j][1] *= r0; o[j][2] *= r1; o[j][3] *= r1;
        }

#pragma unroll
        for (int jj = 0; jj < 2; jj++) {
#pragma unroll
            for (int np = 0; np < 4; np++) {
                uint32_t vaddr = kvb + 2*KVPL + (jj*16 + (lane & 15)) * FROW + (np*16 + (lane >> 4)*8) * 2;
                uint32_t vh[4], vl[4];
                ldsm4t(vh, vaddr);
                ldsm4t(vl, vaddr + KVPL);
                uint32_t bh0[2] = {vh[0], vh[1]}, bh1[2] = {vh[2], vh[3]};
                uint32_t bl0[2] = {vl[0], vl[1]}, bl1[2] = {vl[2], vl[3]};
                mma_bf16(o[2*np],   aph[jj], bh0);
                mma_bf16(o[2*np],   aph[jj], bl0);
                mma_bf16(o[2*np],   apl[jj], bh0);
                mma_bf16(o[2*np+1], aph[jj], bh1);
                mma_bf16(o[2*np+1], aph[jj], bl1);
                mma_bf16(o[2*np+1], apl[jj], bh1);
            }
        }
    }

    float inv0 = 1.f / l0, inv1 = 1.f / l1;
    const size_t rA = rowbase + q0 + wq + (lane >> 2);
    const size_t rB = rA + 8;
#pragma unroll
    for (int j = 0; j < 8; j++) {
        int col = hoff + j * 8 + (lane & 3) * 2;
        uint32_t h0, lo0, h1, lo1;
        splitpack(o[j][0] * inv0, o[j][1] * inv0, h0, lo0);
        splitpack(o[j][2] * inv1, o[j][3] * inv1, h1, lo1);
        *(uint32_t*)(Oh + rA * DM + col) = h0;
        *(uint32_t*)(Ol + rA * DM + col) = lo0;
        *(uint32_t*)(Oh + rB * DM + col) = h1;
        *(uint32_t*)(Ol + rB * DM + col) = lo1;
    }
}

// ---------------------------------------------------------------------------
extern "C" void kernel_launch(void* const* d_in, const int* in_sizes, int n_in,
                              void* d_out, int out_size)
{
    const float* x      = (const float*)d_in[0];  // [4,2048,1024]
    const float* w_qkv  = (const float*)d_in[1];  // [3072,1024]
    const float* w_proj = (const float*)d_in[2];  // [1024,1024]
    float* out = (float*)d_out;                   // [4,2048,1024]

    void *qh_p, *ql_p, *ah_p, *al_p, *wh_p, *wl_p, *xh_p, *wh16_p, *wl16_p;
    cudaGetSymbolAddress(&qh_p, g_qkvh);
    cudaGetSymbolAddress(&ql_p, g_qkvl);
    cudaGetSymbolAddress(&ah_p, g_ah);
    cudaGetSymbolAddress(&al_p, g_al);
    cudaGetSymbolAddress(&wh_p, g_wh);
    cudaGetSymbolAddress(&wl_p, g_wl);
    cudaGetSymbolAddress(&xh_p, g_xh);
    cudaGetSymbolAddress(&wh16_p, g_wh16);
    cudaGetSymbolAddress(&wl16_p, g_wl16);
    __nv_bfloat16 *qkvh = (__nv_bfloat16*)qh_p, *qkvl = (__nv_bfloat16*)ql_p;
    __nv_bfloat16 *ah = (__nv_bfloat16*)ah_p, *al = (__nv_bfloat16*)al_p;
    __nv_bfloat16 *wh = (__nv_bfloat16*)wh_p, *wl = (__nv_bfloat16*)wl_p;
    __half *xh = (__half*)xh_p, *wh16 = (__half*)wh16_p, *wl16 = (__half*)wl16_p;

    cudaFuncSetAttribute(gemm_f16a1, cudaFuncAttributeMaxDynamicSharedMemorySize, F16SMEM);
    cudaFuncSetAttribute(gemm_bf16,  cudaFuncAttributeMaxDynamicSharedMemorySize, GSMEM);
    cudaFuncSetAttribute(flash_tc,   cudaFuncAttributeMaxDynamicSharedMemorySize, FSMEM);

    const int nX = M_TOT * DM, nWq = 3 * DM * DM, nWp = DM * DM;
    const float CSC = 0.125f * 1.4426950408889634f;   // softmax scale * log2(e)

    // 1) x -> fp16 single; w_qkv -> fp16 2-term split; qkv = x @ w_qkv^T
    //    (fp16 single-A GEMM, 2 MMAs/slab; Q section pre-scaled by CSC)
    cvt_f16<<<nX / 1024, 256>>>(x, xh, nX);
    split_f16<<<nWq / 1024, 256>>>(w_qkv, wh16, wl16, nWq);
    gemm_f16a1<<<dim3(3*DM/128, M_TOT/128), 256, F16SMEM>>>(
        xh, wh16, wl16, qkvh, qkvl, 3*DM, DM, CSC);

    // 2) tensor-core flash attention (bf16 3-term, unchanged) -> att planes
    flash_tc<<<dim3(TT/128, BB*NH), 256, FSMEM>>>(qkvh, qkvl, ah, al);

    // 3) w_proj -> bf16 split; out = att @ w_proj^T (bf16 3-term, fp32 out)
    split_bf16<<<nWp / 1024, 256>>>(w_proj, wh, wl, nWp);
    gemm_bf16<<<dim3(DM/128, M_TOT/128), 256, GSMEM>>>(
        ah, al, wh, wl, out, DM, DM);
}

// round 15
// speedup vs baseline: 1.7245x; 1.4183x over previous
#include <cuda_runtime.h>
#include <cuda_bf16.h>
#include <cuda_fp16.h>
#include <math.h>
#include <stdint.h>

#define BB 4
#define TT 2048
#define DM 1024
#define NH 16
#define DH 64
#define M_TOT (BB*TT)   // 8192

// Scratch (allocation-free rule: device globals)
__device__ __half        g_qkv16[(size_t)BB*TT*3*DM]; // qkv single fp16 [B,T,3D]
__device__ __nv_bfloat16 g_ah[(size_t)M_TOT*DM];      // att-split hi (bf16, flash out)
__device__ __nv_bfloat16 g_al[(size_t)M_TOT*DM];      // (lo)
__device__ __nv_bfloat16 g_wh[(size_t)DM*DM];         // w_proj split hi (bf16)
__device__ __nv_bfloat16 g_wl[(size_t)DM*DM];         // (lo)
__device__ __half        g_xh[(size_t)M_TOT*DM];      // x as single fp16
__device__ __half        g_wh16[(size_t)3*DM*DM];     // w_qkv fp16 split hi
__device__ __half        g_wl16[(size_t)3*DM*DM];     // w_qkv fp16 split lo

// ===========================================================================
// Portable (sm_100 base target) tensor-core primitives. tcgen05 is sm_100a-
// only and this harness compiles at sm_100 — mma.sync/ldmatrix/cp.async only.
// ===========================================================================
__device__ __forceinline__ uint32_t smem_u32(const void* p) {
    uint32_t a;
    asm("{ .reg .u64 t; cvta.to.shared.u64 t, %1; cvt.u32.u64 %0, t; }" : "=r"(a) : "l"(p));
    return a;
}
__device__ __forceinline__ void ldsm4(uint32_t* r, uint32_t addr) {
    asm volatile("ldmatrix.sync.aligned.m8n8.x4.shared.b16 {%0,%1,%2,%3}, [%4];"
        : "=r"(r[0]), "=r"(r[1]), "=r"(r[2]), "=r"(r[3]) : "r"(addr));
}
__device__ __forceinline__ void ldsm4t(uint32_t* r, uint32_t addr) {
    asm volatile("ldmatrix.sync.aligned.m8n8.x4.trans.shared.b16 {%0,%1,%2,%3}, [%4];"
        : "=r"(r[0]), "=r"(r[1]), "=r"(r[2]), "=r"(r[3]) : "r"(addr));
}
__device__ __forceinline__ void ldsm2(uint32_t* r, uint32_t addr) {
    asm volatile("ldmatrix.sync.aligned.m8n8.x2.shared.b16 {%0,%1}, [%2];"
        : "=r"(r[0]), "=r"(r[1]) : "r"(addr));
}
__device__ __forceinline__ void mma_bf16(float* d, const uint32_t* a, const uint32_t* b) {
    asm volatile("mma.sync.aligned.m16n8k16.row.col.f32.bf16.bf16.f32 "
        "{%0,%1,%2,%3}, {%4,%5,%6,%7}, {%8,%9}, {%0,%1,%2,%3};"
        : "+f"(d[0]), "+f"(d[1]), "+f"(d[2]), "+f"(d[3])
        : "r"(a[0]), "r"(a[1]), "r"(a[2]), "r"(a[3]), "r"(b[0]), "r"(b[1]));
}
__device__ __forceinline__ void mma_f16(float* d, const uint32_t* a, const uint32_t* b) {
    asm volatile("mma.sync.aligned.m16n8k16.row.col.f32.f16.f16.f32 "
        "{%0,%1,%2,%3}, {%4,%5,%6,%7}, {%8,%9}, {%0,%1,%2,%3};"
        : "+f"(d[0]), "+f"(d[1]), "+f"(d[2]), "+f"(d[3])
        : "r"(a[0]), "r"(a[1]), "r"(a[2]), "r"(a[3]), "r"(b[0]), "r"(b[1]));
}
#define CP_ASYNC16(s, g) \
    asm volatile("cp.async.cg.shared.global [%0], [%1], 16;" :: "r"(s), "l"(g))
#define CP_COMMIT() asm volatile("cp.async.commit_group;" ::: "memory")
template <int N> __device__ __forceinline__ void cp_wait() {
    asm volatile("cp.async.wait_group %0;" :: "n"(N) : "memory");
}
__device__ __forceinline__ float ex2(float x) {
    float y;
    asm("ex2.approx.ftz.f32 %0, %1;" : "=f"(y) : "f"(x));
    return y;
}
__device__ __forceinline__ void splitpack(float a, float b, uint32_t& hi, uint32_t& lo) {
    __nv_bfloat16 ha = __float2bfloat16(a), hb = __float2bfloat16(b);
    __nv_bfloat16 la = __float2bfloat16(a - __bfloat162float(ha));
    __nv_bfloat16 lb = __float2bfloat16(b - __bfloat162float(hb));
    hi = (uint32_t)__bfloat16_as_ushort(ha) | ((uint32_t)__bfloat16_as_ushort(hb) << 16);
    lo = (uint32_t)__bfloat16_as_ushort(la) | ((uint32_t)__bfloat16_as_ushort(lb) << 16);
}
__device__ __forceinline__ void splitpack_h(float a, float b, uint32_t& hi, uint32_t& lo) {
    __half ha = __float2half_rn(a), hb = __float2half_rn(b);
    __half la = __float2half_rn(a - __half2float(ha));
    __half lb = __float2half_rn(b - __half2float(hb));
    hi = (uint32_t)__half_as_ushort(ha) | ((uint32_t)__half_as_ushort(hb) << 16);
    lo = (uint32_t)__half_as_ushort(la) | ((uint32_t)__half_as_ushort(lb) << 16);
}
__device__ __forceinline__ uint32_t packh(float a, float b) {
    __half2 t = __floats2half2_rn(a, b);
    return *(uint32_t*)&t;
}

// ===========================================================================
// conversion passes
// ===========================================================================
__global__ __launch_bounds__(256) void split_bf16(
    const float* __restrict__ src, __nv_bfloat16* __restrict__ hi,
    __nv_bfloat16* __restrict__ lo, int n)
{
    int i = (blockIdx.x * 256 + threadIdx.x) * 4;
    if (i >= n) return;
    float4 v = *(const float4*)(src + i);
    uint2 hp, lp;
    splitpack(v.x, v.y, hp.x, lp.x);
    splitpack(v.z, v.w, hp.y, lp.y);
    *(uint2*)(hi + i) = hp;
    *(uint2*)(lo + i) = lp;
}
__global__ __launch_bounds__(256) void split_f16(
    const float* __restrict__ src, __half* __restrict__ hi,
    __half* __restrict__ lo, int n)
{
    int i = (blockIdx.x * 256 + threadIdx.x) * 4;
    if (i >= n) return;
    float4 v = *(const float4*)(src + i);
    uint2 hp, lp;
    splitpack_h(v.x, v.y, hp.x, lp.x);
    splitpack_h(v.z, v.w, hp.y, lp.y);
    *(uint2*)(hi + i) = hp;
    *(uint2*)(lo + i) = lp;
}
__global__ __launch_bounds__(256) void cvt_f16(
    const float* __restrict__ src, __half* __restrict__ dst, int n)
{
    int i = (blockIdx.x * 256 + threadIdx.x) * 4;
    if (i >= n) return;
    float4 v = *(const float4*)(src + i);
    uint2 p;
    p.x = packh(v.x, v.y);
    p.y = packh(v.z, v.w);
    *(uint2*)(dst + i) = p;
}

// ===========================================================================
// fp16 single-A GEMM (NT) for qkv: C = A * B^T, A single fp16, B fp16 2-term.
// CTA 128x128, 8 warps, BK=32, 2-stage, two barriers/chunk, 2 CTAs/SM.
// Epilogue: qscale on Q section; writes SINGLE fp16 plane (feeds fp16 flash).
// ===========================================================================
#define BK 32
#define PBYTES (128*80)              // one plane per stage: 10240 B
#define FSTG   (3*PBYTES)            // A, Bh, Bl
#define F16SMEM (2*FSTG)             // 61440 B

__global__ __launch_bounds__(256, 2) void gemm_f16a1(
    const __half* __restrict__ A1,
    const __half* __restrict__ Bh, const __half* __restrict__ Bl,
    __half* __restrict__ C16, int N, int K, float qscale)
{
    extern __shared__ char smem[];
    const uint32_t sb = smem_u32(smem);
    const int tid = threadIdx.x, lane = tid & 31, wid = tid >> 5;
    const int wm = wid >> 2, wn = wid & 3;
    const int mBlk = blockIdx.y * 128, nBlk = blockIdx.x * 128;

    float acc[4][4][4];
#pragma unroll
    for (int mt = 0; mt < 4; mt++)
#pragma unroll
        for (int nt = 0; nt < 4; nt++)
#pragma unroll
            for (int j = 0; j < 4; j++) acc[mt][nt][j] = 0.f;

    const int NCH = K / BK;

    auto load_stage = [&](int s, int k0) {
        uint32_t so = sb + (s ? FSTG : 0);
#pragma unroll
        for (int i = tid; i < 512; i += 256) {
            int r = i >> 2, ch = i & 3;
            uint32_t d = so + (uint32_t)r * 80 + ch * 16;
            size_t goA = (size_t)(mBlk + r) * K + k0 + ch * 8;
            size_t goB = (size_t)(nBlk + r) * K + k0 + ch * 8;
            CP_ASYNC16(d,            A1 + goA);
            CP_ASYNC16(d + PBYTES,   Bh + goB);
            CP_ASYNC16(d + 2*PBYTES, Bl + goB);
        }
        CP_COMMIT();
    };

    load_stage(0, 0);

    for (int c = 0; c < NCH; c++) {
        if (c + 1 < NCH) { load_stage((c + 1) & 1, (c + 1) * BK); cp_wait<1>(); }
        else             { cp_wait<0>(); }
        __syncthreads();

        uint32_t so = sb + ((c & 1) ? FSTG : 0);
        const uint32_t aRow = wm * 64 + (lane & 15);
        const uint32_t bRow = wn * 32 + (lane & 7);
#pragma unroll
        for (int ks = 0; ks < 2; ks++) {
            const uint32_t ak = ks * 16 + (lane >> 4) * 8;
            const uint32_t bk = ks * 16 + ((lane >> 3) & 1) * 8;
            uint32_t ah[4][4];
#pragma unroll
            for (int mt = 0; mt < 4; mt++)
                ldsm4(ah[mt], so + (aRow + mt * 16) * 80 + ak * 2);
#pragma unroll
            for (int nt = 0; nt < 4; nt++) {
                uint32_t baddr = so + PBYTES + (bRow + nt * 8) * 80 + bk * 2;
                uint32_t bh[2], bl[2];
                ldsm2(bh, baddr);
                ldsm2(bl, baddr + PBYTES);
#pragma unroll
                for (int mt = 0; mt < 4; mt++) {
                    mma_f16(acc[mt][nt], ah[mt], bh);
                    mma_f16(acc[mt][nt], ah[mt], bl);
                }
            }
        }
        __syncthreads();
    }

    const float sc = (nBlk < DM) ? qscale : 1.0f;
    const int row0 = mBlk + wm * 64, col0 = nBlk + wn * 32;
#pragma unroll
    for (int mt = 0; mt < 4; mt++) {
        int r = row0 + mt * 16 + (lane >> 2);
#pragma unroll
        for (int nt = 0; nt < 4; nt++) {
            int cc = col0 + nt * 8 + (lane & 3) * 2;
            *(uint32_t*)(C16 + (size_t)r * N + cc)       = packh(acc[mt][nt][0] * sc, acc[mt][nt][1] * sc);
            *(uint32_t*)(C16 + (size_t)(r + 8) * N + cc) = packh(acc[mt][nt][2] * sc, acc[mt][nt][3] * sc);
        }
    }
}

// ===========================================================================
// HMMA bf16-split GEMM (NT) — exact R10 version (proj only).
// ===========================================================================
#define ABYTES (128*80)
#define STG    (4*ABYTES)
#define GSMEM  (2*STG)               // 81920 B

__global__ __launch_bounds__(256, 2) void gemm_bf16(
    const __nv_bfloat16* __restrict__ Ah, const __nv_bfloat16* __restrict__ Al,
    const __nv_bfloat16* __restrict__ Bh, const __nv_bfloat16* __restrict__ Bl,
    float* __restrict__ C, int N, int K)
{
    extern __shared__ char smem[];
    const uint32_t sb = smem_u32(smem);
    const int tid = threadIdx.x, lane = tid & 31, wid = tid >> 5;
    const int wm = wid >> 2, wn = wid & 3;
    const int mBlk = blockIdx.y * 128, nBlk = blockIdx.x * 128;

    float acc[4][4][4];
#pragma unroll
    for (int mt = 0; mt < 4; mt++)
#pragma unroll
        for (int nt = 0; nt < 4; nt++)
#pragma unroll
            for (int j = 0; j < 4; j++) acc[mt][nt][j] = 0.f;

    const int NCH = K / BK;

    auto load_stage = [&](int s, int k0) {
        uint32_t so = sb + (s ? STG : 0);
#pragma unroll
        for (int i = tid; i < 512; i += 256) {
            int r = i >> 2, ch = i & 3;
            uint32_t d = so + (uint32_t)r * 80 + ch * 16;
            size_t goA = (size_t)(mBlk + r) * K + k0 + ch * 8;
            size_t goB = (size_t)(nBlk + r) * K + k0 + ch * 8;
            CP_ASYNC16(d,            Ah + goA);
            CP_ASYNC16(d + ABYTES,   Al + goA);
            CP_ASYNC16(d + 2*ABYTES, Bh + goB);
            CP_ASYNC16(d + 3*ABYTES, Bl + goB);
        }
        CP_COMMIT();
    };

    load_stage(0, 0);

    for (int c = 0; c < NCH; c++) {
        if (c + 1 < NCH) { load_stage((c + 1) & 1, (c + 1) * BK); cp_wait<1>(); }
        else             { cp_wait<0>(); }
        __syncthreads();

        uint32_t so = sb + ((c & 1) ? STG : 0);
        const uint32_t aRow = wm * 64 + (lane & 15);
        const uint32_t bRow = wn * 32 + (lane & 7);
#pragma unroll
        for (int ks = 0; ks < 2; ks++) {
            const uint32_t ak = ks * 16 + (lane >> 4) * 8;
            const uint32_t bk = ks * 16 + ((lane >> 3) & 1) * 8;
            uint32_t ah[4][4], al[4][4];
#pragma unroll
            for (int mt = 0; mt < 4; mt++) {
                uint32_t addr = so + (aRow + mt * 16) * 80 + ak * 2;
                ldsm4(ah[mt], addr);
                ldsm4(al[mt], addr + ABYTES);
            }
#pragma unroll
            for (int nt = 0; nt < 4; nt++) {
                uint32_t baddr = so + 2*ABYTES + (bRow + nt * 8) * 80 + bk * 2;
                uint32_t bh[2], bl[2];
                ldsm2(bh, baddr);
                ldsm2(bl, baddr + ABYTES);
#pragma unroll
                for (int mt = 0; mt < 4; mt++) {
                    mma_bf16(acc[mt][nt], ah[mt], bh);
                    mma_bf16(acc[mt][nt], ah[mt], bl);
                    mma_bf16(acc[mt][nt], al[mt], bh);
                }
            }
        }
        __syncthreads();
    }

    const int row0 = mBlk + wm * 64, col0 = nBlk + wn * 32;
#pragma unroll
    for (int mt = 0; mt < 4; mt++) {
        int r = row0 + mt * 16 + (lane >> 2);
#pragma unroll
        for (int nt = 0; nt < 4; nt++) {
            int cc = col0 + nt * 8 + (lane & 3) * 2;
            *(float2*)(C + (size_t)r * N + cc)       = make_float2(acc[mt][nt][0], acc[mt][nt][1]);
            *(float2*)(C + (size_t)(r + 8) * N + cc) = make_float2(acc[mt][nt][2], acc[mt][nt][3]);
        }
    }
}

// ===========================================================================
// Tensor-core flash attention — FULL fp16 (single-plane Q, K, V, P).
// MMAs/iter: 32 (was 96 with bf16 3-term).  Structure identical to the
// proven R10 kernel: key tile 32, 3-stage cp.async, one barrier/tile,
// 2 CTAs/SM.  Rows 128 B data + 16 B pad.
// smem: Q (128x144) | 3 stages x {K,V} (32x144 each) = 46080 B.
// Epilogue still emits bf16 hi/lo att planes for the bf16 3-term proj.
// ===========================================================================
#define FROW 144
#define QPL  (128*FROW)       // 18432
#define KVPL (32*FROW)        // 4608 per K/V plane
#define SQH 0
#define SKV QPL               // 18432
#define KVSTG (2*KVPL)        // 9216 per stage
#define FSMEM (SKV + 3*KVSTG) // 46080

__global__ __launch_bounds__(256, 2) void flash_tc(
    const __half* __restrict__ P16,
    __nv_bfloat16* __restrict__ Oh, __nv_bfloat16* __restrict__ Ol)
{
    extern __shared__ char smem[];
    const uint32_t sb = smem_u32(smem);
    const int tid = threadIdx.x, lane = tid & 31, wid = tid >> 5;
    const int qt = blockIdx.x, bh = blockIdx.y;
    const int b = bh >> 4, h = bh & 15;
    const size_t rowbase = (size_t)b * TT;
    const int q0 = qt * 128;
    const int hoff = h * DH;

    // ---- Q tile, 128 rows x 64 halves
#pragma unroll
    for (int i = tid; i < 1024; i += 256) {
        int r = i >> 3, ch = i & 7;
        const __half* src = P16 + (rowbase + q0 + r) * 3*DM + hoff + ch * 8;
        CP_ASYNC16(sb + SQH + r * FROW + ch * 16, src);
    }
    auto load_kv = [&](int s, int kt) {
        uint32_t so = sb + SKV + s * KVSTG;
#pragma unroll
        for (int i = tid; i < 512; i += 256) {
            int p = i >> 8, r = (i >> 3) & 31, ch = i & 7;
            int sec = p ? 2*DM : DM;
            const __half* src = P16 + (rowbase + kt*32 + r) * 3*DM + sec + hoff + ch * 8;
            CP_ASYNC16(so + p * KVPL + r * FROW + ch * 16, src);
        }
    };
    load_kv(0, 0);
    CP_COMMIT();
    load_kv(1, 1);
    CP_COMMIT();

    const int wq = wid * 16;
    const int NK = TT / 32;
    float o[8][4];
#pragma unroll
    for (int j = 0; j < 8; j++)
#pragma unroll
        for (int i = 0; i < 4; i++) o[j][i] = 0.f;
    float m0 = -1e30f, m1 = -1e30f, l0 = 0.f, l1 = 0.f;

    for (int kt = 0; kt < NK; kt++) {
        if (kt + 1 < NK) cp_wait<1>(); else cp_wait<0>();
        __syncthreads();
        if (kt + 2 < NK) { load_kv((kt + 2) % 3, kt + 2); CP_COMMIT(); }
        const uint32_t kvb = sb + SKV + (kt % 3) * KVSTG;

        // ---- S = Q K^T  (fp16 single x single), 16q x 32k per warp
        float s[4][4];
#pragma unroll
        for (int j = 0; j < 4; j++)
#pragma unroll
            for (int i = 0; i < 4; i++) s[j][i] = 0.f;
#pragma unroll
        for (int ks = 0; ks < 4; ks++) {
            uint32_t qaddr = sb + SQH + (wq + (lane & 15)) * FROW + (ks*16 + (lane >> 4)*8) * 2;
            uint32_t qh[4];
            ldsm4(qh, qaddr);
#pragma unroll
            for (int np = 0; np < 2; np++) {
                uint32_t kaddr = kvb + (np*16 + (lane & 15)) * FROW + (ks*16 + (lane >> 4)*8) * 2;
                uint32_t kh[4];
                ldsm4(kh, kaddr);
                uint32_t b0h[2] = {kh[0], kh[2]}, b1h[2] = {kh[1], kh[3]};
                mma_f16(s[2*np],   qh, b0h);
                mma_f16(s[2*np+1], qh, b1h);
            }
        }

        // ---- online softmax (log2 domain; scale pre-folded into Q)
        float t0 = -1e30f, t1 = -1e30f;
#pragma unroll
        for (int j = 0; j < 4; j++) {
            t0 = fmaxf(t0, fmaxf(s[j][0], s[j][1]));
            t1 = fmaxf(t1, fmaxf(s[j][2], s[j][3]));
        }
        t0 = fmaxf(t0, __shfl_xor_sync(0xffffffffu, t0, 1));
        t0 = fmaxf(t0, __shfl_xor_sync(0xffffffffu, t0, 2));
        t1 = fmaxf(t1, __shfl_xor_sync(0xffffffffu, t1, 1));
        t1 = fmaxf(t1, __shfl_xor_sync(0xffffffffu, t1, 2));
        float m0n = fmaxf(m0, t0), m1n = fmaxf(m1, t1);
        float r0 = ex2(m0 - m0n), r1 = ex2(m1 - m1n);
        m0 = m0n; m1 = m1n;

        float ls0 = 0.f, ls1 = 0.f;
        uint32_t aph[2][4];
#pragma unroll
        for (int j = 0; j < 4; j++) {
            float p0 = ex2(s[j][0] - m0), p1 = ex2(s[j][1] - m0);
            float p2 = ex2(s[j][2] - m1), p3 = ex2(s[j][3] - m1);
            ls0 += p0 + p1; ls1 += p2 + p3;
            int jj = j >> 1, rb = (j & 1) * 2;
            aph[jj][rb]     = packh(p0, p1);
            aph[jj][rb + 1] = packh(p2, p3);
        }
        ls0 += __shfl_xor_sync(0xffffffffu, ls0, 1);
        ls0 += __shfl_xor_sync(0xffffffffu, ls0, 2);
        ls1 += __shfl_xor_sync(0xffffffffu, ls1, 1);
        ls1 += __shfl_xor_sync(0xffffffffu, ls1, 2);
        l0 = l0 * r0 + ls0;
        l1 = l1 * r1 + ls1;
#pragma unroll
        for (int j = 0; j < 8; j++) {
            o[j][0] *= r0; o[j][1] *= r0; o[j][2] *= r1; o[j][3] *= r1;
        }

        // ---- O += P V  (fp16 single x single), V via ldmatrix.trans
#pragma unroll
        for (int jj = 0; jj < 2; jj++) {
#pragma unroll
            for (int np = 0; np < 4; np++) {
                uint32_t vaddr = kvb + KVPL + (jj*16 + (lane & 15)) * FROW + (np*16 + (lane >> 4)*8) * 2;
                uint32_t vh[4];
                ldsm4t(vh, vaddr);
                uint32_t bh0[2] = {vh[0], vh[1]}, bh1[2] = {vh[2], vh[3]};
                mma_f16(o[2*np],   aph[jj], bh0);
                mma_f16(o[2*np+1], aph[jj], bh1);
            }
        }
    }

    // ---- epilogue: normalize, split, write att bf16 hi/lo planes [B,T,D]
    float inv0 = 1.f / l0, inv1 = 1.f / l1;
    const size_t rA = rowbase + q0 + wq + (lane >> 2);
    const size_t rB = rA + 8;
#pragma unroll
    for (int j = 0; j < 8; j++) {
        int col = hoff + j * 8 + (lane & 3) * 2;
        uint32_t h0, lo0, h1, lo1;
        splitpack(o[j][0] * inv0, o[j][1] * inv0, h0, lo0);
        splitpack(o[j][2] * inv1, o[j][3] * inv1, h1, lo1);
        *(uint32_t*)(Oh + rA * DM + col) = h0;
        *(uint32_t*)(Ol + rA * DM + col) = lo0;
        *(uint32_t*)(Oh + rB * DM + col) = h1;
        *(uint32_t*)(Ol + rB * DM + col) = lo1;
    }
}

// ---------------------------------------------------------------------------
extern "C" void kernel_launch(void* const* d_in, const int* in_sizes, int n_in,
                              void* d_out, int out_size)
{
    const float* x      = (const float*)d_in[0];  // [4,2048,1024]
    const float* w_qkv  = (const float*)d_in[1];  // [3072,1024]
    const float* w_proj = (const float*)d_in[2];  // [1024,1024]
    float* out = (float*)d_out;                   // [4,2048,1024]

    void *q16_p, *ah_p, *al_p, *wh_p, *wl_p, *xh_p, *wh16_p, *wl16_p;
    cudaGetSymbolAddress(&q16_p, g_qkv16);
    cudaGetSymbolAddress(&ah_p, g_ah);
    cudaGetSymbolAddress(&al_p, g_al);
    cudaGetSymbolAddress(&wh_p, g_wh);
    cudaGetSymbolAddress(&wl_p, g_wl);
    cudaGetSymbolAddress(&xh_p, g_xh);
    cudaGetSymbolAddress(&wh16_p, g_wh16);
    cudaGetSymbolAddress(&wl16_p, g_wl16);
    __half *qkv16 = (__half*)q16_p;
    __nv_bfloat16 *ah = (__nv_bfloat16*)ah_p, *al = (__nv_bfloat16*)al_p;
    __nv_bfloat16 *wh = (__nv_bfloat16*)wh_p, *wl = (__nv_bfloat16*)wl_p;
    __half *xh = (__half*)xh_p, *wh16 = (__half*)wh16_p, *wl16 = (__half*)wl16_p;

    cudaFuncSetAttribute(gemm_f16a1, cudaFuncAttributeMaxDynamicSharedMemorySize, F16SMEM);
    cudaFuncSetAttribute(gemm_bf16,  cudaFuncAttributeMaxDynamicSharedMemorySize, GSMEM);
    cudaFuncSetAttribute(flash_tc,   cudaFuncAttributeMaxDynamicSharedMemorySize, FSMEM);

    const int nX = M_TOT * DM, nWq = 3 * DM * DM, nWp = DM * DM;
    const float CSC = 0.125f * 1.4426950408889634f;   // softmax scale * log2(e)

    // 1) x -> fp16; w_qkv -> fp16 2-term split; qkv = x @ w_qkv^T -> fp16 plane
    cvt_f16<<<nX / 1024, 256>>>(x, xh, nX);
    split_f16<<<nWq / 1024, 256>>>(w_qkv, wh16, wl16, nWq);
    gemm_f16a1<<<dim3(3*DM/128, M_TOT/128), 256, F16SMEM>>>(
        xh, wh16, wl16, qkv16, 3*DM, DM, CSC);

    // 2) fp16 flash attention -> att bf16 hi/lo planes
    flash_tc<<<dim3(TT/128, BB*NH), 256, FSMEM>>>(qkv16, ah, al);

    // 3) w_proj -> bf16 split; out = att @ w_proj^T (bf16 3-term, fp32 out)
    split_bf16<<<nWp / 1024, 256>>>(w_proj, wh, wl, nWp);
    gemm_bf16<<<dim3(DM/128, M_TOT/128), 256, GSMEM>>>(
        ah, al, wh, wl, out, DM, DM);
}

// round 16
// speedup vs baseline: 1.9426x; 1.1264x over previous
#include <cuda_runtime.h>
#include <cuda_bf16.h>
#include <cuda_fp16.h>
#include <math.h>
#include <stdint.h>

#define BB 4
#define TT 2048
#define DM 1024
#define NH 16
#define DH 64
#define M_TOT (BB*TT)   // 8192

// Scratch (allocation-free rule: device globals)
__device__ __half g_qkv16[(size_t)BB*TT*3*DM]; // qkv single fp16 [B,T,3D]
__device__ __half g_att16[(size_t)M_TOT*DM];   // att single fp16 (flash out)
__device__ __half g_xh[(size_t)M_TOT*DM];      // x as single fp16
__device__ __half g_wh16[(size_t)3*DM*DM];     // weight fp16 split hi (qkv, then proj)
__device__ __half g_wl16[(size_t)3*DM*DM];     // weight fp16 split lo

// ===========================================================================
// Portable (sm_100 base target) tensor-core primitives. tcgen05 is sm_100a-
// only and this harness compiles at sm_100 — mma.sync/ldmatrix/cp.async only.
// ===========================================================================
__device__ __forceinline__ uint32_t smem_u32(const void* p) {
    uint32_t a;
    asm("{ .reg .u64 t; cvta.to.shared.u64 t, %1; cvt.u32.u64 %0, t; }" : "=r"(a) : "l"(p));
    return a;
}
__device__ __forceinline__ void ldsm4(uint32_t* r, uint32_t addr) {
    asm volatile("ldmatrix.sync.aligned.m8n8.x4.shared.b16 {%0,%1,%2,%3}, [%4];"
        : "=r"(r[0]), "=r"(r[1]), "=r"(r[2]), "=r"(r[3]) : "r"(addr));
}
__device__ __forceinline__ void ldsm4t(uint32_t* r, uint32_t addr) {
    asm volatile("ldmatrix.sync.aligned.m8n8.x4.trans.shared.b16 {%0,%1,%2,%3}, [%4];"
        : "=r"(r[0]), "=r"(r[1]), "=r"(r[2]), "=r"(r[3]) : "r"(addr));
}
__device__ __forceinline__ void ldsm2(uint32_t* r, uint32_t addr) {
    asm volatile("ldmatrix.sync.aligned.m8n8.x2.shared.b16 {%0,%1}, [%2];"
        : "=r"(r[0]), "=r"(r[1]) : "r"(addr));
}
__device__ __forceinline__ void mma_f16(float* d, const uint32_t* a, const uint32_t* b) {
    asm volatile("mma.sync.aligned.m16n8k16.row.col.f32.f16.f16.f32 "
        "{%0,%1,%2,%3}, {%4,%5,%6,%7}, {%8,%9}, {%0,%1,%2,%3};"
        : "+f"(d[0]), "+f"(d[1]), "+f"(d[2]), "+f"(d[3])
        : "r"(a[0]), "r"(a[1]), "r"(a[2]), "r"(a[3]), "r"(b[0]), "r"(b[1]));
}
#define CP_ASYNC16(s, g) \
    asm volatile("cp.async.cg.shared.global [%0], [%1], 16;" :: "r"(s), "l"(g))
#define CP_COMMIT() asm volatile("cp.async.commit_group;" ::: "memory")
template <int N> __device__ __forceinline__ void cp_wait() {
    asm volatile("cp.async.wait_group %0;" :: "n"(N) : "memory");
}
__device__ __forceinline__ float ex2(float x) {
    float y;
    asm("ex2.approx.ftz.f32 %0, %1;" : "=f"(y) : "f"(x));
    return y;
}
__device__ __forceinline__ void splitpack_h(float a, float b, uint32_t& hi, uint32_t& lo) {
    __half ha = __float2half_rn(a), hb = __float2half_rn(b);
    __half la = __float2half_rn(a - __half2float(ha));
    __half lb = __float2half_rn(b - __half2float(hb));
    hi = (uint32_t)__half_as_ushort(ha) | ((uint32_t)__half_as_ushort(hb) << 16);
    lo = (uint32_t)__half_as_ushort(la) | ((uint32_t)__half_as_ushort(lb) << 16);
}
__device__ __forceinline__ uint32_t packh(float a, float b) {
    __half2 t = __floats2half2_rn(a, b);
    return *(uint32_t*)&t;
}

// ===========================================================================
// conversion passes
// ===========================================================================
__global__ __launch_bounds__(256) void split_f16(
    const float* __restrict__ src, __half* __restrict__ hi,
    __half* __restrict__ lo, int n)
{
    int i = (blockIdx.x * 256 + threadIdx.x) * 4;
    if (i >= n) return;
    float4 v = *(const float4*)(src + i);
    uint2 hp, lp;
    splitpack_h(v.x, v.y, hp.x, lp.x);
    splitpack_h(v.z, v.w, hp.y, lp.y);
    *(uint2*)(hi + i) = hp;
    *(uint2*)(lo + i) = lp;
}
__global__ __launch_bounds__(256) void cvt_f16(
    const float* __restrict__ src, __half* __restrict__ dst, int n)
{
    int i = (blockIdx.x * 256 + threadIdx.x) * 4;
    if (i >= n) return;
    float4 v = *(const float4*)(src + i);
    uint2 p;
    p.x = packh(v.x, v.y);
    p.y = packh(v.z, v.w);
    *(uint2*)(dst + i) = p;
}

// ===========================================================================
// fp16 single-A GEMM (NT): C = A * B^T, A single fp16, B fp16 2-term split.
// CTA 128x128, 8 warps, BK=32, 2-stage, two barriers/chunk, 2 CTAs/SM.
// OUT16=true: write fp16 plane (qkv; qscale on Q section).
// OUT16=false: write fp32 (proj; qscale=1).
// ===========================================================================
#define BK 32
#define PBYTES (128*80)              // one plane per stage: 10240 B
#define FSTG   (3*PBYTES)            // A, Bh, Bl
#define F16SMEM (2*FSTG)             // 61440 B

template <bool OUT16>
__global__ __launch_bounds__(256, 2) void gemm_f16a1(
    const __half* __restrict__ A1,
    const __half* __restrict__ Bh, const __half* __restrict__ Bl,
    __half* __restrict__ C16, float* __restrict__ C32,
    int N, int K, float qscale)
{
    extern __shared__ char smem[];
    const uint32_t sb = smem_u32(smem);
    const int tid = threadIdx.x, lane = tid & 31, wid = tid >> 5;
    const int wm = wid >> 2, wn = wid & 3;
    const int mBlk = blockIdx.y * 128, nBlk = blockIdx.x * 128;

    float acc[4][4][4];
#pragma unroll
    for (int mt = 0; mt < 4; mt++)
#pragma unroll
        for (int nt = 0; nt < 4; nt++)
#pragma unroll
            for (int j = 0; j < 4; j++) acc[mt][nt][j] = 0.f;

    const int NCH = K / BK;

    auto load_stage = [&](int s, int k0) {
        uint32_t so = sb + (s ? FSTG : 0);
#pragma unroll
        for (int i = tid; i < 512; i += 256) {
            int r = i >> 2, ch = i & 3;
            uint32_t d = so + (uint32_t)r * 80 + ch * 16;
            size_t goA = (size_t)(mBlk + r) * K + k0 + ch * 8;
            size_t goB = (size_t)(nBlk + r) * K + k0 + ch * 8;
            CP_ASYNC16(d,            A1 + goA);
            CP_ASYNC16(d + PBYTES,   Bh + goB);
            CP_ASYNC16(d + 2*PBYTES, Bl + goB);
        }
        CP_COMMIT();
    };

    load_stage(0, 0);

    for (int c = 0; c < NCH; c++) {
        if (c + 1 < NCH) { load_stage((c + 1) & 1, (c + 1) * BK); cp_wait<1>(); }
        else             { cp_wait<0>(); }
        __syncthreads();

        uint32_t so = sb + ((c & 1) ? FSTG : 0);
        const uint32_t aRow = wm * 64 + (lane & 15);
        const uint32_t bRow = wn * 32 + (lane & 7);
#pragma unroll
        for (int ks = 0; ks < 2; ks++) {
            const uint32_t ak = ks * 16 + (lane >> 4) * 8;
            const uint32_t bk = ks * 16 + ((lane >> 3) & 1) * 8;
            uint32_t ah[4][4];
#pragma unroll
            for (int mt = 0; mt < 4; mt++)
                ldsm4(ah[mt], so + (aRow + mt * 16) * 80 + ak * 2);
#pragma unroll
            for (int nt = 0; nt < 4; nt++) {
                uint32_t baddr = so + PBYTES + (bRow + nt * 8) * 80 + bk * 2;
                uint32_t bh[2], bl[2];
                ldsm2(bh, baddr);
                ldsm2(bl, baddr + PBYTES);
#pragma unroll
                for (int mt = 0; mt < 4; mt++) {
                    mma_f16(acc[mt][nt], ah[mt], bh);
                    mma_f16(acc[mt][nt], ah[mt], bl);
                }
            }
        }
        __syncthreads();
    }

    const float sc = (nBlk < DM) ? qscale : 1.0f;
    const int row0 = mBlk + wm * 64, col0 = nBlk + wn * 32;
#pragma unroll
    for (int mt = 0; mt < 4; mt++) {
        int r = row0 + mt * 16 + (lane >> 2);
#pragma unroll
        for (int nt = 0; nt < 4; nt++) {
            int cc = col0 + nt * 8 + (lane & 3) * 2;
            if (OUT16) {
                *(uint32_t*)(C16 + (size_t)r * N + cc)       = packh(acc[mt][nt][0] * sc, acc[mt][nt][1] * sc);
                *(uint32_t*)(C16 + (size_t)(r + 8) * N + cc) = packh(acc[mt][nt][2] * sc, acc[mt][nt][3] * sc);
            } else {
                *(float2*)(C32 + (size_t)r * N + cc)       = make_float2(acc[mt][nt][0], acc[mt][nt][1]);
                *(float2*)(C32 + (size_t)(r + 8) * N + cc) = make_float2(acc[mt][nt][2], acc[mt][nt][3]);
            }
        }
    }
}

// ===========================================================================
// Tensor-core flash attention — fp16 single-plane, KEY TILE 64.
// fp16 fragments (s+aph = 48 regs vs 96 for bf16 3-term) let tile 64 fit
// ~128 regs at 2 CTAs/SM, halving per-iteration softmax fixed costs
// (o-rescale, shuffles, m/l updates) vs tile 32.  64 MMAs/iter, 32 iters.
// 3-stage cp.async, one barrier/tile.  Rows 128 B data + 16 B pad.
// smem: Q (128x144) | 3 stages x {K,V} (64x144 each) = 73728 B (x2 CTAs ok).
// Epilogue writes att as a SINGLE fp16 plane (feeds fp16 proj GEMM).
// ===========================================================================
#define FROW 144
#define QPL  (128*FROW)       // 18432
#define KVPL (64*FROW)        // 9216 per K/V plane
#define SQH 0
#define SKV QPL               // 18432
#define KVSTG (2*KVPL)        // 18432 per stage
#define FSMEM (SKV + 3*KVSTG) // 73728

__global__ __launch_bounds__(256, 2) void flash_tc(
    const __half* __restrict__ P16, __half* __restrict__ O16)
{
    extern __shared__ char smem[];
    const uint32_t sb = smem_u32(smem);
    const int tid = threadIdx.x, lane = tid & 31, wid = tid >> 5;
    const int qt = blockIdx.x, bh = blockIdx.y;
    const int b = bh >> 4, h = bh & 15;
    const size_t rowbase = (size_t)b * TT;
    const int q0 = qt * 128;
    const int hoff = h * DH;

    // ---- Q tile, 128 rows x 64 halves
#pragma unroll
    for (int i = tid; i < 1024; i += 256) {
        int r = i >> 3, ch = i & 7;
        const __half* src = P16 + (rowbase + q0 + r) * 3*DM + hoff + ch * 8;
        CP_ASYNC16(sb + SQH + r * FROW + ch * 16, src);
    }
    auto load_kv = [&](int s, int kt) {
        uint32_t so = sb + SKV + s * KVSTG;
#pragma unroll
        for (int i = tid; i < 1024; i += 256) {
            int p = i >> 9, r = (i >> 3) & 63, ch = i & 7;
            int sec = p ? 2*DM : DM;
            const __half* src = P16 + (rowbase + kt*64 + r) * 3*DM + sec + hoff + ch * 8;
            CP_ASYNC16(so + p * KVPL + r * FROW + ch * 16, src);
        }
    };
    load_kv(0, 0);
    CP_COMMIT();
    load_kv(1, 1);
    CP_COMMIT();

    const int wq = wid * 16;
    const int NK = TT / 64;
    float o[8][4];
#pragma unroll
    for (int j = 0; j < 8; j++)
#pragma unroll
        for (int i = 0; i < 4; i++) o[j][i] = 0.f;
    float m0 = -1e30f, m1 = -1e30f, l0 = 0.f, l1 = 0.f;

    for (int kt = 0; kt < NK; kt++) {
        if (kt + 1 < NK) cp_wait<1>(); else cp_wait<0>();
        __syncthreads();
        if (kt + 2 < NK) { load_kv((kt + 2) % 3, kt + 2); CP_COMMIT(); }
        const uint32_t kvb = sb + SKV + (kt % 3) * KVSTG;

        // ---- S = Q K^T  (fp16 single x single), 16q x 64k per warp
        float s[8][4];
#pragma unroll
        for (int j = 0; j < 8; j++)
#pragma unroll
            for (int i = 0; i < 4; i++) s[j][i] = 0.f;
#pragma unroll
        for (int ks = 0; ks < 4; ks++) {
            uint32_t qaddr = sb + SQH + (wq + (lane & 15)) * FROW + (ks*16 + (lane >> 4)*8) * 2;
            uint32_t qh[4];
            ldsm4(qh, qaddr);
#pragma unroll
            for (int np = 0; np < 4; np++) {
                uint32_t kaddr = kvb + (np*16 + (lane & 15)) * FROW + (ks*16 + (lane >> 4)*8) * 2;
                uint32_t kh[4];
                ldsm4(kh, kaddr);
                uint32_t b0h[2] = {kh[0], kh[2]}, b1h[2] = {kh[1], kh[3]};
                mma_f16(s[2*np],   qh, b0h);
                mma_f16(s[2*np+1], qh, b1h);
            }
        }

        // ---- online softmax (log2 domain; scale pre-folded into Q)
        float t0 = -1e30f, t1 = -1e30f;
#pragma unroll
        for (int j = 0; j < 8; j++) {
            t0 = fmaxf(t0, fmaxf(s[j][0], s[j][1]));
            t1 = fmaxf(t1, fmaxf(s[j][2], s[j][3]));
        }
        t0 = fmaxf(t0, __shfl_xor_sync(0xffffffffu, t0, 1));
        t0 = fmaxf(t0, __shfl_xor_sync(0xffffffffu, t0, 2));
        t1 = fmaxf(t1, __shfl_xor_sync(0xffffffffu, t1, 1));
        t1 = fmaxf(t1, __shfl_xor_sync(0xffffffffu, t1, 2));
        float m0n = fmaxf(m0, t0), m1n = fmaxf(m1, t1);
        float r0 = ex2(m0 - m0n), r1 = ex2(m1 - m1n);
        m0 = m0n; m1 = m1n;

        float ls0 = 0.f, ls1 = 0.f;
        uint32_t aph[4][4];
#pragma unroll
        for (int j = 0; j < 8; j++) {
            float p0 = ex2(s[j][0] - m0), p1 = ex2(s[j][1] - m0);
            float p2 = ex2(s[j][2] - m1), p3 = ex2(s[j][3] - m1);
            ls0 += p0 + p1; ls1 += p2 + p3;
            int jj = j >> 1, rb = (j & 1) * 2;
            aph[jj][rb]     = packh(p0, p1);
            aph[jj][rb + 1] = packh(p2, p3);
        }
        ls0 += __shfl_xor_sync(0xffffffffu, ls0, 1);
        ls0 += __shfl_xor_sync(0xffffffffu, ls0, 2);
        ls1 += __shfl_xor_sync(0xffffffffu, ls1, 1);
        ls1 += __shfl_xor_sync(0xffffffffu, ls1, 2);
        l0 = l0 * r0 + ls0;
        l1 = l1 * r1 + ls1;
#pragma unroll
        for (int j = 0; j < 8; j++) {
            o[j][0] *= r0; o[j][1] *= r0; o[j][2] *= r1; o[j][3] *= r1;
        }

        // ---- O += P V  (fp16 single x single), V via ldmatrix.trans
#pragma unroll
        for (int jj = 0; jj < 4; jj++) {
#pragma unroll
            for (int np = 0; np < 4; np++) {
                uint32_t vaddr = kvb + KVPL + (jj*16 + (lane & 15)) * FROW + (np*16 + (lane >> 4)*8) * 2;
                uint32_t vh[4];
                ldsm4t(vh, vaddr);
                uint32_t bh0[2] = {vh[0], vh[1]}, bh1[2] = {vh[2], vh[3]};
                mma_f16(o[2*np],   aph[jj], bh0);
                mma_f16(o[2*np+1], aph[jj], bh1);
            }
        }
    }

    // ---- epilogue: normalize, write att single fp16 plane [B,T,D]
    float inv0 = 1.f / l0, inv1 = 1.f / l1;
    const size_t rA = rowbase + q0 + wq + (lane >> 2);
    const size_t rB = rA + 8;
#pragma unroll
    for (int j = 0; j < 8; j++) {
        int col = hoff + j * 8 + (lane & 3) * 2;
        *(uint32_t*)(O16 + rA * DM + col) = packh(o[j][0] * inv0, o[j][1] * inv0);
        *(uint32_t*)(O16 + rB * DM + col) = packh(o[j][2] * inv1, o[j][3] * inv1);
    }
}

// ---------------------------------------------------------------------------
extern "C" void kernel_launch(void* const* d_in, const int* in_sizes, int n_in,
                              void* d_out, int out_size)
{
    const float* x      = (const float*)d_in[0];  // [4,2048,1024]
    const float* w_qkv  = (const float*)d_in[1];  // [3072,1024]
    const float* w_proj = (const float*)d_in[2];  // [1024,1024]
    float* out = (float*)d_out;                   // [4,2048,1024]

    void *q16_p, *a16_p, *xh_p, *wh16_p, *wl16_p;
    cudaGetSymbolAddress(&q16_p, g_qkv16);
    cudaGetSymbolAddress(&a16_p, g_att16);
    cudaGetSymbolAddress(&xh_p, g_xh);
    cudaGetSymbolAddress(&wh16_p, g_wh16);
    cudaGetSymbolAddress(&wl16_p, g_wl16);
    __half *qkv16 = (__half*)q16_p, *att16 = (__half*)a16_p;
    __half *xh = (__half*)xh_p, *wh16 = (__half*)wh16_p, *wl16 = (__half*)wl16_p;

    cudaFuncSetAttribute(gemm_f16a1<true>,  cudaFuncAttributeMaxDynamicSharedMemorySize, F16SMEM);
    cudaFuncSetAttribute(gemm_f16a1<false>, cudaFuncAttributeMaxDynamicSharedMemorySize, F16SMEM);
    cudaFuncSetAttribute(flash_tc, cudaFuncAttributeMaxDynamicSharedMemorySize, FSMEM);

    const int nX = M_TOT * DM, nWq = 3 * DM * DM, nWp = DM * DM;
    const float CSC = 0.125f * 1.4426950408889634f;   // softmax scale * log2(e)

    // 1) x -> fp16; w_qkv -> fp16 2-term split; qkv = x @ w_qkv^T -> fp16 plane
    cvt_f16<<<nX / 1024, 256>>>(x, xh, nX);
    split_f16<<<nWq / 1024, 256>>>(w_qkv, wh16, wl16, nWq);
    gemm_f16a1<true><<<dim3(3*DM/128, M_TOT/128), 256, F16SMEM>>>(
        xh, wh16, wl16, qkv16, nullptr, 3*DM, DM, CSC);

    // 2) fp16 flash attention (key tile 64) -> att single fp16 plane
    flash_tc<<<dim3(TT/128, BB*NH), 256, FSMEM>>>(qkv16, att16);

    // 3) w_proj -> fp16 2-term split (reuse wh16/wl16 — qkv GEMM has drained);
    //    out = att @ w_proj^T  (fp16 single-A, fp32 out)
    split_f16<<<nWp / 1024, 256>>>(w_proj, wh16, wl16, nWp);
    gemm_f16a1<false><<<dim3(DM/128, M_TOT/128), 256, F16SMEM>>>(
        att16, wh16, wl16, nullptr, out, DM, DM, 1.0f);
}

// round 17
// speedup vs baseline: 2.6407x; 1.3594x over previous
#include <cuda_runtime.h>
#include <cuda_bf16.h>
#include <cuda_fp16.h>
#include <math.h>
#include <stdint.h>

#define BB 4
#define TT 2048
#define DM 1024
#define NH 16
#define DH 64
#define M_TOT (BB*TT)   // 8192

// Scratch (allocation-free rule: device globals)
__device__ __half g_qkv16[(size_t)BB*TT*3*DM]; // qkv single fp16 [B,T,3D]
__device__ __half g_att16[(size_t)M_TOT*DM];   // att single fp16 (flash out)
__device__ __half g_xh[(size_t)M_TOT*DM];      // x as single fp16
__device__ __half g_w16[(size_t)3*DM*DM];      // weight single fp16 (qkv, then proj)

// ===========================================================================
// Portable (sm_100 base target) tensor-core primitives. tcgen05 is sm_100a-
// only and this harness compiles at sm_100 — mma.sync/ldmatrix/cp.async only.
// ===========================================================================
__device__ __forceinline__ uint32_t smem_u32(const void* p) {
    uint32_t a;
    asm("{ .reg .u64 t; cvta.to.shared.u64 t, %1; cvt.u32.u64 %0, t; }" : "=r"(a) : "l"(p));
    return a;
}
__device__ __forceinline__ void ldsm4(uint32_t* r, uint32_t addr) {
    asm volatile("ldmatrix.sync.aligned.m8n8.x4.shared.b16 {%0,%1,%2,%3}, [%4];"
        : "=r"(r[0]), "=r"(r[1]), "=r"(r[2]), "=r"(r[3]) : "r"(addr));
}
__device__ __forceinline__ void ldsm4t(uint32_t* r, uint32_t addr) {
    asm volatile("ldmatrix.sync.aligned.m8n8.x4.trans.shared.b16 {%0,%1,%2,%3}, [%4];"
        : "=r"(r[0]), "=r"(r[1]), "=r"(r[2]), "=r"(r[3]) : "r"(addr));
}
__device__ __forceinline__ void ldsm2(uint32_t* r, uint32_t addr) {
    asm volatile("ldmatrix.sync.aligned.m8n8.x2.shared.b16 {%0,%1}, [%2];"
        : "=r"(r[0]), "=r"(r[1]) : "r"(addr));
}
__device__ __forceinline__ void mma_f16(float* d, const uint32_t* a, const uint32_t* b) {
    asm volatile("mma.sync.aligned.m16n8k16.row.col.f32.f16.f16.f32 "
        "{%0,%1,%2,%3}, {%4,%5,%6,%7}, {%8,%9}, {%0,%1,%2,%3};"
        : "+f"(d[0]), "+f"(d[1]), "+f"(d[2]), "+f"(d[3])
        : "r"(a[0]), "r"(a[1]), "r"(a[2]), "r"(a[3]), "r"(b[0]), "r"(b[1]));
}
#define CP_ASYNC16(s, g) \
    asm volatile("cp.async.cg.shared.global [%0], [%1], 16;" :: "r"(s), "l"(g))
#define CP_COMMIT() asm volatile("cp.async.commit_group;" ::: "memory")
template <int N> __device__ __forceinline__ void cp_wait() {
    asm volatile("cp.async.wait_group %0;" :: "n"(N) : "memory");
}
__device__ __forceinline__ float ex2(float x) {
    float y;
    asm("ex2.approx.ftz.f32 %0, %1;" : "=f"(y) : "f"(x));
    return y;
}
__device__ __forceinline__ uint32_t packh(float a, float b) {
    __half2 t = __floats2half2_rn(a, b);
    return *(uint32_t*)&t;
}

// ===========================================================================
// conversion pass: fp32 -> fp16 single
// ===========================================================================
__global__ __launch_bounds__(256) void cvt_f16(
    const float* __restrict__ src, __half* __restrict__ dst, int n)
{
    int i = (blockIdx.x * 256 + threadIdx.x) * 4;
    if (i >= n) return;
    float4 v = *(const float4*)(src + i);
    uint2 p;
    p.x = packh(v.x, v.y);
    p.y = packh(v.z, v.w);
    *(uint2*)(dst + i) = p;
}

// ===========================================================================
// fp16 single x single GEMM (NT): C = A * B^T, fp32 accumulate.
// CTA 128x128, 8 warps (2x4), BK=32, 2-stage, two barriers/chunk, 2 CTAs/SM.
// Rows padded 64B->80B.  32 MMAs/chunk.
// OUT16=true: write fp16 plane (qkv; qscale on Q section).
// OUT16=false: write fp32 (proj; qscale=1).
// ===========================================================================
#define BK 32
#define PBYTES (128*80)              // one plane per stage: 10240 B
#define GSTG   (2*PBYTES)            // A, B
#define G16SMEM (2*GSTG)             // 40960 B

template <bool OUT16>
__global__ __launch_bounds__(256, 2) void gemm_f16(
    const __half* __restrict__ A1, const __half* __restrict__ B1,
    __half* __restrict__ C16, float* __restrict__ C32,
    int N, int K, float qscale)
{
    extern __shared__ char smem[];
    const uint32_t sb = smem_u32(smem);
    const int tid = threadIdx.x, lane = tid & 31, wid = tid >> 5;
    const int wm = wid >> 2, wn = wid & 3;
    const int mBlk = blockIdx.y * 128, nBlk = blockIdx.x * 128;

    float acc[4][4][4];
#pragma unroll
    for (int mt = 0; mt < 4; mt++)
#pragma unroll
        for (int nt = 0; nt < 4; nt++)
#pragma unroll
            for (int j = 0; j < 4; j++) acc[mt][nt][j] = 0.f;

    const int NCH = K / BK;

    auto load_stage = [&](int s, int k0) {
        uint32_t so = sb + (s ? GSTG : 0);
#pragma unroll
        for (int i = tid; i < 512; i += 256) {
            int r = i >> 2, ch = i & 3;
            uint32_t d = so + (uint32_t)r * 80 + ch * 16;
            size_t goA = (size_t)(mBlk + r) * K + k0 + ch * 8;
            size_t goB = (size_t)(nBlk + r) * K + k0 + ch * 8;
            CP_ASYNC16(d,          A1 + goA);
            CP_ASYNC16(d + PBYTES, B1 + goB);
        }
        CP_COMMIT();
    };

    load_stage(0, 0);

    for (int c = 0; c < NCH; c++) {
        if (c + 1 < NCH) { load_stage((c + 1) & 1, (c + 1) * BK); cp_wait<1>(); }
        else             { cp_wait<0>(); }
        __syncthreads();

        uint32_t so = sb + ((c & 1) ? GSTG : 0);
        const uint32_t aRow = wm * 64 + (lane & 15);
        const uint32_t bRow = wn * 32 + (lane & 7);
#pragma unroll
        for (int ks = 0; ks < 2; ks++) {
            const uint32_t ak = ks * 16 + (lane >> 4) * 8;
            const uint32_t bk = ks * 16 + ((lane >> 3) & 1) * 8;
            uint32_t ah[4][4];
#pragma unroll
            for (int mt = 0; mt < 4; mt++)
                ldsm4(ah[mt], so + (aRow + mt * 16) * 80 + ak * 2);
#pragma unroll
            for (int nt = 0; nt < 4; nt++) {
                uint32_t bh[2];
                ldsm2(bh, so + PBYTES + (bRow + nt * 8) * 80 + bk * 2);
#pragma unroll
                for (int mt = 0; mt < 4; mt++)
                    mma_f16(acc[mt][nt], ah[mt], bh);
            }
        }
        __syncthreads();
    }

    const float sc = (nBlk < DM) ? qscale : 1.0f;
    const int row0 = mBlk + wm * 64, col0 = nBlk + wn * 32;
#pragma unroll
    for (int mt = 0; mt < 4; mt++) {
        int r = row0 + mt * 16 + (lane >> 2);
#pragma unroll
        for (int nt = 0; nt < 4; nt++) {
            int cc = col0 + nt * 8 + (lane & 3) * 2;
            if (OUT16) {
                *(uint32_t*)(C16 + (size_t)r * N + cc)       = packh(acc[mt][nt][0] * sc, acc[mt][nt][1] * sc);
                *(uint32_t*)(C16 + (size_t)(r + 8) * N + cc) = packh(acc[mt][nt][2] * sc, acc[mt][nt][3] * sc);
            } else {
                *(float2*)(C32 + (size_t)r * N + cc)       = make_float2(acc[mt][nt][0], acc[mt][nt][1]);
                *(float2*)(C32 + (size_t)(r + 8) * N + cc) = make_float2(acc[mt][nt][2], acc[mt][nt][3]);
            }
        }
    }
}

// ===========================================================================
// Tensor-core flash attention — fp16 single-plane, key tile 64 (R16, 255 µs).
// 64 MMAs/iter, 32 iters, 3-stage cp.async, one barrier/tile, 2 CTAs/SM.
// smem: Q (128x144) | 3 stages x {K,V} (64x144 each) = 73728 B.
// ===========================================================================
#define FROW 144
#define QPL  (128*FROW)       // 18432
#define KVPL (64*FROW)        // 9216 per K/V plane
#define SQH 0
#define SKV QPL               // 18432
#define KVSTG (2*KVPL)        // 18432 per stage
#define FSMEM (SKV + 3*KVSTG) // 73728

__global__ __launch_bounds__(256, 2) void flash_tc(
    const __half* __restrict__ P16, __half* __restrict__ O16)
{
    extern __shared__ char smem[];
    const uint32_t sb = smem_u32(smem);
    const int tid = threadIdx.x, lane = tid & 31, wid = tid >> 5;
    const int qt = blockIdx.x, bh = blockIdx.y;
    const int b = bh >> 4, h = bh & 15;
    const size_t rowbase = (size_t)b * TT;
    const int q0 = qt * 128;
    const int hoff = h * DH;

    // ---- Q tile, 128 rows x 64 halves
#pragma unroll
    for (int i = tid; i < 1024; i += 256) {
        int r = i >> 3, ch = i & 7;
        const __half* src = P16 + (rowbase + q0 + r) * 3*DM + hoff + ch * 8;
        CP_ASYNC16(sb + SQH + r * FROW + ch * 16, src);
    }
    auto load_kv = [&](int s, int kt) {
        uint32_t so = sb + SKV + s * KVSTG;
#pragma unroll
        for (int i = tid; i < 1024; i += 256) {
            int p = i >> 9, r = (i >> 3) & 63, ch = i & 7;
            int sec = p ? 2*DM : DM;
            const __half* src = P16 + (rowbase + kt*64 + r) * 3*DM + sec + hoff + ch * 8;
            CP_ASYNC16(so + p * KVPL + r * FROW + ch * 16, src);
        }
    };
    load_kv(0, 0);
    CP_COMMIT();
    load_kv(1, 1);
    CP_COMMIT();

    const int wq = wid * 16;
    const int NK = TT / 64;
    float o[8][4];
#pragma unroll
    for (int j = 0; j < 8; j++)
#pragma unroll
        for (int i = 0; i < 4; i++) o[j][i] = 0.f;
    float m0 = -1e30f, m1 = -1e30f, l0 = 0.f, l1 = 0.f;

    for (int kt = 0; kt < NK; kt++) {
        if (kt + 1 < NK) cp_wait<1>(); else cp_wait<0>();
        __syncthreads();
        if (kt + 2 < NK) { load_kv((kt + 2) % 3, kt + 2); CP_COMMIT(); }
        const uint32_t kvb = sb + SKV + (kt % 3) * KVSTG;

        // ---- S = Q K^T  (fp16 single x single), 16q x 64k per warp
        float s[8][4];
#pragma unroll
        for (int j = 0; j < 8; j++)
#pragma unroll
            for (int i = 0; i < 4; i++) s[j][i] = 0.f;
#pragma unroll
        for (int ks = 0; ks < 4; ks++) {
            uint32_t qaddr = sb + SQH + (wq + (lane & 15)) * FROW + (ks*16 + (lane >> 4)*8) * 2;
            uint32_t qh[4];
            ldsm4(qh, qaddr);
#pragma unroll
            for (int np = 0; np < 4; np++) {
                uint32_t kaddr = kvb + (np*16 + (lane & 15)) * FROW + (ks*16 + (lane >> 4)*8) * 2;
                uint32_t kh[4];
                ldsm4(kh, kaddr);
                uint32_t b0h[2] = {kh[0], kh[2]}, b1h[2] = {kh[1], kh[3]};
                mma_f16(s[2*np],   qh, b0h);
                mma_f16(s[2*np+1], qh, b1h);
            }
        }

        // ---- online softmax (log2 domain; scale pre-folded into Q)
        float t0 = -1e30f, t1 = -1e30f;
#pragma unroll
        for (int j = 0; j < 8; j++) {
            t0 = fmaxf(t0, fmaxf(s[j][0], s[j][1]));
            t1 = fmaxf(t1, fmaxf(s[j][2], s[j][3]));
        }
        t0 = fmaxf(t0, __shfl_xor_sync(0xffffffffu, t0, 1));
        t0 = fmaxf(t0, __shfl_xor_sync(0xffffffffu, t0, 2));
        t1 = fmaxf(t1, __shfl_xor_sync(0xffffffffu, t1, 1));
        t1 = fmaxf(t1, __shfl_xor_sync(0xffffffffu, t1, 2));
        float m0n = fmaxf(m0, t0), m1n = fmaxf(m1, t1);
        float r0 = ex2(m0 - m0n), r1 = ex2(m1 - m1n);
        m0 = m0n; m1 = m1n;

        float ls0 = 0.f, ls1 = 0.f;
        uint32_t aph[4][4];
#pragma unroll
        for (int j = 0; j < 8; j++) {
            float p0 = ex2(s[j][0] - m0), p1 = ex2(s[j][1] - m0);
            float p2 = ex2(s[j][2] - m1), p3 = ex2(s[j][3] - m1);
            ls0 += p0 + p1; ls1 += p2 + p3;
            int jj = j >> 1, rb = (j & 1) * 2;
            aph[jj][rb]     = packh(p0, p1);
            aph[jj][rb + 1] = packh(p2, p3);
        }
        ls0 += __shfl_xor_sync(0xffffffffu, ls0, 1);
        ls0 += __shfl_xor_sync(0xffffffffu, ls0, 2);
        ls1 += __shfl_xor_sync(0xffffffffu, ls1, 1);
        ls1 += __shfl_xor_sync(0xffffffffu, ls1, 2);
        l0 = l0 * r0 + ls0;
        l1 = l1 * r1 + ls1;
#pragma unroll
        for (int j = 0; j < 8; j++) {
            o[j][0] *= r0; o[j][1] *= r0; o[j][2] *= r1; o[j][3] *= r1;
        }

        // ---- O += P V  (fp16 single x single), V via ldmatrix.trans
#pragma unroll
        for (int jj = 0; jj < 4; jj++) {
#pragma unroll
            for (int np = 0; np < 4; np++) {
                uint32_t vaddr = kvb + KVPL + (jj*16 + (lane & 15)) * FROW + (np*16 + (lane >> 4)*8) * 2;
                uint32_t vh[4];
                ldsm4t(vh, vaddr);
                uint32_t bh0[2] = {vh[0], vh[1]}, bh1[2] = {vh[2], vh[3]};
                mma_f16(o[2*np],   aph[jj], bh0);
                mma_f16(o[2*np+1], aph[jj], bh1);
            }
        }
    }

    // ---- epilogue: normalize, write att single fp16 plane [B,T,D]
    float inv0 = 1.f / l0, inv1 = 1.f / l1;
    const size_t rA = rowbase + q0 + wq + (lane >> 2);
    const size_t rB = rA + 8;
#pragma unroll
    for (int j = 0; j < 8; j++) {
        int col = hoff + j * 8 + (lane & 3) * 2;
        *(uint32_t*)(O16 + rA * DM + col) = packh(o[j][0] * inv0, o[j][1] * inv0);
        *(uint32_t*)(O16 + rB * DM + col) = packh(o[j][2] * inv1, o[j][3] * inv1);
    }
}

// ---------------------------------------------------------------------------
extern "C" void kernel_launch(void* const* d_in, const int* in_sizes, int n_in,
                              void* d_out, int out_size)
{
    const float* x      = (const float*)d_in[0];  // [4,2048,1024]
    const float* w_qkv  = (const float*)d_in[1];  // [3072,1024]
    const float* w_proj = (const float*)d_in[2];  // [1024,1024]
    float* out = (float*)d_out;                   // [4,2048,1024]

    void *q16_p, *a16_p, *xh_p, *w16_p;
    cudaGetSymbolAddress(&q16_p, g_qkv16);
    cudaGetSymbolAddress(&a16_p, g_att16);
    cudaGetSymbolAddress(&xh_p, g_xh);
    cudaGetSymbolAddress(&w16_p, g_w16);
    __half *qkv16 = (__half*)q16_p, *att16 = (__half*)a16_p;
    __half *xh = (__half*)xh_p, *w16 = (__half*)w16_p;

    cudaFuncSetAttribute(gemm_f16<true>,  cudaFuncAttributeMaxDynamicSharedMemorySize, G16SMEM);
    cudaFuncSetAttribute(gemm_f16<false>, cudaFuncAttributeMaxDynamicSharedMemorySize, G16SMEM);
    cudaFuncSetAttribute(flash_tc, cudaFuncAttributeMaxDynamicSharedMemorySize, FSMEM);

    const int nX = M_TOT * DM, nWq = 3 * DM * DM, nWp = DM * DM;
    const float CSC = 0.125f * 1.4426950408889634f;   // softmax scale * log2(e)

    // 1) x, w_qkv -> fp16; qkv = x @ w_qkv^T -> fp16 plane (Q pre-scaled)
    cvt_f16<<<nX / 1024, 256>>>(x, xh, nX);
    cvt_f16<<<nWq / 1024, 256>>>(w_qkv, w16, nWq);
    gemm_f16<true><<<dim3(3*DM/128, M_TOT/128), 256, G16SMEM>>>(
        xh, w16, qkv16, nullptr, 3*DM, DM, CSC);

    // 2) fp16 flash attention (key tile 64) -> att single fp16 plane
    flash_tc<<<dim3(TT/128, BB*NH), 256, FSMEM>>>(qkv16, att16);

    // 3) w_proj -> fp16 (reuse g_w16); out = att @ w_proj^T (fp32 out)
    cvt_f16<<<nWp / 1024, 256>>>(w_proj, w16, nWp);
    gemm_f16<false><<<dim3(DM/128, M_TOT/128), 256, G16SMEM>>>(
        att16, w16, nullptr, out, DM, DM, 1.0f);
}